// round 2
// baseline (speedup 1.0000x reference)
#include <cuda_runtime.h>

// ---------------- problem constants ----------------
#define NH   8          // heads
#define NT   4          // stacks
#define NB   4          // batch
#define SQ   1024       // seq len
#define NV   256        // value / feature dim
#define NKD  64         // key dim
#define RR   4096       // NB*SQ rows
#define NZ   32         // NH*NB
#define EPSBN 1e-3f

// ---------------- device scratch (allocation-free rule: __device__ globals) ----
__device__ float g_net [(long)NH*RR*NV];   // 8M  (32MB)
__device__ float g_net0[(long)RR*NV];      // 1M  (4MB)
__device__ float g_q   [(long)NH*RR*NKD];  // 2M  (8MB)
__device__ float g_k   [(long)NH*RR*NKD];  // 2M  (8MB)
__device__ float g_v   [(long)NH*RR*NV];   // 8M  (32MB)
__device__ float g_tmp [(long)NH*RR*NV];   // 8M  (32MB)
__device__ float g_sc  [(long)NZ*SQ*SQ];   // 32M (128MB)
__device__ float g_stats[2*NH*NV];

// ---------------- batched tiled GEMM: C = A @ B (or A @ B^T) -------------------
// Tile 128x64x16, 256 threads, 8x4 microtile per thread. All dims are multiples
// of the tile sizes for every call site (M in {1024,4096}, N in {64,256,1024},
// K in {64,256,1024}), so no bounds checks.
template<bool TB>
__global__ void __launch_bounds__(256) gemm_k(
    const float* __restrict__ Ab, const float* __restrict__ Bb, float* __restrict__ Cb,
    int M, int N, int K, long sA, long sB, long sC)
{
    const int BM = 128, BN = 64, BK = 16;
    const float* A = Ab + (long)blockIdx.z * sA;
    const float* Bm = Bb + (long)blockIdx.z * sB;
    float*       C = Cb + (long)blockIdx.z * sC;

    __shared__ float As[BK][BM];
    __shared__ float Bs[BK][BN];

    int tid = threadIdx.x;
    int tx = tid & 15;        // 0..15 -> N
    int ty = tid >> 4;        // 0..15 -> M
    int row0 = blockIdx.y * BM;
    int col0 = blockIdx.x * BN;

    float acc[8][4];
    #pragma unroll
    for (int i = 0; i < 8; i++)
        #pragma unroll
        for (int j = 0; j < 4; j++) acc[i][j] = 0.f;

    for (int k0 = 0; k0 < K; k0 += BK) {
        // load A tile 128x16 (2 float4 per thread), store transposed
        #pragma unroll
        for (int l = 0; l < 2; l++) {
            int lin = tid + l * 256;
            int r   = lin >> 2;
            int kk  = (lin & 3) << 2;
            float4 a = *(const float4*)(A + (long)(row0 + r) * K + k0 + kk);
            As[kk+0][r] = a.x; As[kk+1][r] = a.y; As[kk+2][r] = a.z; As[kk+3][r] = a.w;
        }
        if (TB) {
            // B is N x K row-major; tile rows col0..col0+63, cols k0..k0+15
            int n  = tid >> 2;          // 0..63
            int kk = (tid & 3) << 2;
            float4 b = *(const float4*)(Bm + (long)(col0 + n) * K + k0 + kk);
            Bs[kk+0][n] = b.x; Bs[kk+1][n] = b.y; Bs[kk+2][n] = b.z; Bs[kk+3][n] = b.w;
        } else {
            // B is K x N row-major; tile 16x64
            int kk = tid >> 4;          // 0..15
            int n4 = (tid & 15) << 2;
            float4 b = *(const float4*)(Bm + (long)(k0 + kk) * N + col0 + n4);
            *(float4*)&Bs[kk][n4] = b;
        }
        __syncthreads();

        #pragma unroll
        for (int kk = 0; kk < BK; ++kk) {
            float4 a0 = *(const float4*)&As[kk][ty * 8];
            float4 a1 = *(const float4*)&As[kk][ty * 8 + 4];
            float4 b0 = *(const float4*)&Bs[kk][tx * 4];
            float ar[8] = {a0.x, a0.y, a0.z, a0.w, a1.x, a1.y, a1.z, a1.w};
            float br[4] = {b0.x, b0.y, b0.z, b0.w};
            #pragma unroll
            for (int i = 0; i < 8; i++)
                #pragma unroll
                for (int j = 0; j < 4; j++)
                    acc[i][j] = fmaf(ar[i], br[j], acc[i][j]);
        }
        __syncthreads();
    }

    #pragma unroll
    for (int i = 0; i < 8; i++) {
        float4 o = make_float4(acc[i][0], acc[i][1], acc[i][2], acc[i][3]);
        *(float4*)(C + (long)(row0 + ty * 8 + i) * N + col0 + tx * 4) = o;
    }
}

// ---------------- row softmax over 1024 cols, scale 1/8 ------------------------
__global__ void __launch_bounds__(256) softmax_k(float* __restrict__ sc)
{
    __shared__ float red[8];
    float* p = sc + (long)blockIdx.x * SQ;
    int tid = threadIdx.x;
    float x[4];
    #pragma unroll
    for (int j = 0; j < 4; j++) x[j] = p[tid + j * 256] * 0.125f;
    float m = fmaxf(fmaxf(x[0], x[1]), fmaxf(x[2], x[3]));
    #pragma unroll
    for (int o = 16; o; o >>= 1) m = fmaxf(m, __shfl_xor_sync(0xffffffffu, m, o));
    if ((tid & 31) == 0) red[tid >> 5] = m;
    __syncthreads();
    #pragma unroll
    for (int w = 0; w < 8; w++) m = fmaxf(m, red[w]);
    float s = 0.f;
    #pragma unroll
    for (int j = 0; j < 4; j++) { x[j] = expf(x[j] - m); s += x[j]; }
    #pragma unroll
    for (int o = 16; o; o >>= 1) s += __shfl_xor_sync(0xffffffffu, s, o);
    __syncthreads();
    if ((tid & 31) == 0) red[tid >> 5] = s;
    __syncthreads();
    s = 0.f;
    #pragma unroll
    for (int w = 0; w < 8; w++) s += red[w];
    float inv = 1.f / s;
    #pragma unroll
    for (int j = 0; j < 4; j++) p[tid + j * 256] = x[j] * inv;
}

// ---------------- residual add (+ optional relu on addend) + per-channel stats -
__global__ void __launch_bounds__(256) resid_reduce_k(
    float* __restrict__ net, const float* __restrict__ add,
    float* __restrict__ stats, int relu)
{
    int h = blockIdx.y, chunk = blockIdx.x, c = threadIdx.x;
    long base = ((long)h * RR + (long)chunk * 64) * NV + c;
    float s = 0.f, s2 = 0.f;
    #pragma unroll 4
    for (int r = 0; r < 64; r++) {
        long idx = base + (long)r * NV;
        float a = add[idx];
        if (relu) a = fmaxf(a, 0.f);
        float val = net[idx] + a;
        net[idx] = val;
        s += val; s2 += val * val;
    }
    atomicAdd(&stats[h * NV + c], s);
    atomicAdd(&stats[NH * NV + h * NV + c], s2);
}

// ---------------- batchnorm apply ----------------------------------------------
__global__ void __launch_bounds__(256) bn_apply_k(
    float* __restrict__ net, const float* __restrict__ stats,
    const float* __restrict__ gamma, const float* __restrict__ beta, int t)
{
    long idx = (long)blockIdx.x * 256 + threadIdx.x;       // over NH*RR*NV
    int c = (int)(idx & (NV - 1));
    int h = (int)(idx >> 20);                              // RR*NV = 2^20
    float mean = stats[h * NV + c] * (1.f / RR);
    float ex2  = stats[NH * NV + h * NV + c] * (1.f / RR);
    float var  = ex2 - mean * mean;
    float g = gamma[(h * NT + t) * NV + c];
    float b = beta [(h * NT + t) * NV + c];
    net[idx] = (net[idx] - mean) * rsqrtf(var + EPSBN) * g + b;
}

// ---------------- broadcast net0 -> net[h] --------------------------------------
__global__ void __launch_bounds__(256) bcast_k(float* __restrict__ net,
                                               const float* __restrict__ net0)
{
    long idx = (long)blockIdx.x * 256 + threadIdx.x;       // over RR*NV
    float v = net0[idx];
    #pragma unroll
    for (int h = 0; h < NH; h++) net[(long)h * RR * NV + idx] = v;
}

// ---------------- final transpose to [B,S,H,V] ----------------------------------
__global__ void __launch_bounds__(256) final_k(float* __restrict__ out,
                                               const float* __restrict__ net)
{
    long idx = (long)blockIdx.x * 256 + threadIdx.x;       // over NB*SQ*NH*NV
    int c = (int)(idx & (NV - 1));
    int h = (int)((idx >> 8) & (NH - 1));
    long bs = idx >> 11;                                   // NH*NV = 2048
    out[idx] = net[((long)h * RR + bs) * NV + c];
}

// ---------------- host orchestration --------------------------------------------
extern "C" void kernel_launch(void* const* d_in, const int* in_sizes, int n_in,
                              void* d_out, int out_size)
{
    (void)in_sizes; (void)n_in; (void)out_size;
    const float* x    = (const float*)d_in[0];
    const float* W_in = (const float*)d_in[1];
    const float* Wq   = (const float*)d_in[2];
    const float* Wk   = (const float*)d_in[3];
    const float* Wv   = (const float*)d_in[4];
    const float* Wd   = (const float*)d_in[5];
    const float* g1   = (const float*)d_in[6];
    const float* b1   = (const float*)d_in[7];
    const float* g2   = (const float*)d_in[8];
    const float* b2   = (const float*)d_in[9];
    float* out = (float*)d_out;

    float *net, *net0, *q, *k, *v, *tmp, *sc, *stats;
    cudaGetSymbolAddress((void**)&net,   g_net);
    cudaGetSymbolAddress((void**)&net0,  g_net0);
    cudaGetSymbolAddress((void**)&q,     g_q);
    cudaGetSymbolAddress((void**)&k,     g_k);
    cudaGetSymbolAddress((void**)&v,     g_v);
    cudaGetSymbolAddress((void**)&tmp,   g_tmp);
    cudaGetSymbolAddress((void**)&sc,    g_sc);
    cudaGetSymbolAddress((void**)&stats, g_stats);

    const long RV = (long)RR * NV;     // 1048576
    const long RK = (long)RR * NKD;    // 262144
    const long SS = (long)SQ * SQ;     // 1048576

    // net0 = x @ W_in   [4096,256] = [4096,256]@[256,256]
    gemm_k<false><<<dim3(NV / 64, RR / 128, 1), 256>>>(
        x, W_in, net0, RR, NV, 256, 0, 0, 0);
    bcast_k<<<(int)(RV / 256), 256>>>(net, net0);

    for (int t = 0; t < NT; t++) {
        // q = net @ Wq[h][t]  [4096,64]
        gemm_k<false><<<dim3(NKD / 64, RR / 128, NH), 256>>>(
            net, Wq + (long)t * NV * NKD, q, RR, NKD, NV,
            RV, (long)NT * NV * NKD, RK);
        // k = net @ Wk[h][t]
        gemm_k<false><<<dim3(NKD / 64, RR / 128, NH), 256>>>(
            net, Wk + (long)t * NV * NKD, k, RR, NKD, NV,
            RV, (long)NT * NV * NKD, RK);
        // v = net @ Wv[h][t]  [4096,256]
        gemm_k<false><<<dim3(NV / 64, RR / 128, NH), 256>>>(
            net, Wv + (long)t * NV * NV, v, RR, NV, NV,
            RV, (long)NT * NV * NV, RV);
        // scores[z] = q[z] @ k[z]^T   z = h*4+b, [1024,1024], K=64
        gemm_k<true><<<dim3(SQ / 64, SQ / 128, NZ), 256>>>(
            q, k, sc, SQ, SQ, NKD,
            (long)SQ * NKD, (long)SQ * NKD, SS);
        softmax_k<<<NZ * SQ, 256>>>(sc);
        // tmp[z] = sc[z] @ v[z]   [1024,256]
        gemm_k<false><<<dim3(NV / 64, SQ / 128, NZ), 256>>>(
            sc, v, tmp, SQ, NV, SQ,
            SS, (long)SQ * NV, (long)SQ * NV);
        // BN1: net = BN(net + tmp)
        cudaMemsetAsync(stats, 0, sizeof(float) * 2 * NH * NV);
        resid_reduce_k<<<dim3(RR / 64, NH), 256>>>(net, tmp, stats, 0);
        bn_apply_k<<<(int)((NH * RV) / 256), 256>>>(net, stats, g1, b1, t);
        // dense: tmp = net @ Wd[h][t]
        gemm_k<false><<<dim3(NV / 64, RR / 128, NH), 256>>>(
            net, Wd + (long)t * NV * NV, tmp, RR, NV, NV,
            RV, (long)NT * NV * NV, RV);
        // BN2: net = BN(net + relu(tmp))
        cudaMemsetAsync(stats, 0, sizeof(float) * 2 * NH * NV);
        resid_reduce_k<<<dim3(RR / 64, NH), 256>>>(net, tmp, stats, 1);
        bn_apply_k<<<(int)((NH * RV) / 256), 256>>>(net, stats, g2, b2, t);
    }

    final_k<<<(int)(((long)NB * SQ * NH * NV) / 256), 256>>>(out, net);
}

// round 9
// speedup vs baseline: 1.2703x; 1.2703x over previous
#include <cuda_runtime.h>
#include <cuda_bf16.h>
#include <mma.h>
#include <cstdint>

using namespace nvcuda;

#define NH   8
#define NT   4
#define NB   4
#define SQ   1024
#define NV   256
#define NKD  64
#define RR   4096
#define NZ   32
#define EPSBN 1e-3f

typedef __nv_bfloat16 bf16;

__device__ float g_net [(long)NH*RR*NV];
__device__ float g_net0[(long)RR*NV];
__device__ float g_tmp [(long)NH*RR*NV];
__device__ float g_stats[2*NH*NV];
__device__ float g_scF [(long)NZ*SQ*SQ];
__device__ float g_qF  [(long)NH*RR*NKD];
__device__ float g_kF  [(long)NH*RR*NKD];
__device__ float g_vF  [(long)NH*RR*NV];

__device__ bf16 g_netH[(long)NH*RR*NV];
__device__ bf16 g_netL[(long)NH*RR*NV];
__device__ bf16 g_qH[(long)NH*RR*NKD];
__device__ bf16 g_qL[(long)NH*RR*NKD];
__device__ bf16 g_kH[(long)NH*RR*NKD];
__device__ bf16 g_kL[(long)NH*RR*NKD];
__device__ bf16 g_vH[(long)NH*RR*NV];
__device__ bf16 g_vL[(long)NH*RR*NV];
__device__ bf16 g_scH[(long)NZ*SQ*SQ];
__device__ bf16 g_scL[(long)NZ*SQ*SQ];
__device__ bf16 g_xH[(long)RR*256];
__device__ bf16 g_xL[(long)RR*256];
__device__ bf16 g_WinH[256*NV];
__device__ bf16 g_WinL[256*NV];
__device__ bf16 g_WqH[NH*NT*NV*NKD];
__device__ bf16 g_WqL[NH*NT*NV*NKD];
__device__ bf16 g_WkH[NH*NT*NV*NKD];
__device__ bf16 g_WkL[NH*NT*NV*NKD];
__device__ bf16 g_WvH[NH*NT*NV*NV];
__device__ bf16 g_WvL[NH*NT*NV*NV];
__device__ bf16 g_WdH[NH*NT*NV*NV];
__device__ bf16 g_WdL[NH*NT*NV*NV];

__device__ __forceinline__ void split2(float v, bf16& h, bf16& l) {
    h = __float2bfloat16(v);
    l = __float2bfloat16(v - __bfloat162float(h));
}

// bf16x3 GEMM via wmma. C = A times B (TB=0) or A times B-transpose (TB=1).
// A: [M,K] row-major hi/lo bf16. B: [K,N] row-major (TB=0) or [N,K] row-major (TB=1).
// C: fp32 [M,N]. Block tile 128x64x32, 256 threads = 8 warps in a 4x2 grid,
// each warp owns a 32x32 output tile (2x2 wmma 16x16 fragments).
#define BM 128
#define BN 64
#define BK 32
#define AST 48
#define BSTN 80
#define BSTT 48

template<int TB>
__global__ void __launch_bounds__(256) gemmW_k(
    const bf16* __restrict__ AH, const bf16* __restrict__ AL,
    const bf16* __restrict__ BH, const bf16* __restrict__ BL,
    float* __restrict__ C,
    int M, int N, int K, long sA, long sB, long sC)
{
    __shared__ bf16 sAH[BM*AST];
    __shared__ bf16 sAL[BM*AST];
    __shared__ bf16 sBH[3072];
    __shared__ bf16 sBL[3072];

    const bf16* pAH = AH + (long)blockIdx.z * sA;
    const bf16* pAL = AL + (long)blockIdx.z * sA;
    const bf16* pBH = BH + (long)blockIdx.z * sB;
    const bf16* pBL = BL + (long)blockIdx.z * sB;
    float* pC = C + (long)blockIdx.z * sC;

    int tid = threadIdx.x;
    int row0 = blockIdx.y * BM;
    int col0 = blockIdx.x * BN;
    int warp = tid >> 5;
    int wm = warp & 3;
    int wn = warp >> 2;

    wmma::fragment<wmma::accumulator, 16, 16, 16, float> acc[2][2];
    for (int i = 0; i < 2; i++)
        for (int j = 0; j < 2; j++)
            wmma::fill_fragment(acc[i][j], 0.0f);

    for (int k0 = 0; k0 < K; k0 += BK) {
        // A tile: 128 x 32 into sAH/sAL with row stride AST
        for (int l = 0; l < 2; l++) {
            int lin = tid + l * 256;
            int r = lin >> 2;
            int c8 = (lin & 3) << 3;
            long g = (long)(row0 + r) * K + k0 + c8;
            *(float4*)&sAH[r * AST + c8] = *(const float4*)(pAH + g);
            *(float4*)&sAL[r * AST + c8] = *(const float4*)(pAL + g);
        }
        // B tile
        if (TB) {
            // B is [N,K] row-major; tile [BN rows x BK cols], row stride BSTT
            int n = tid >> 2;
            int c8 = (tid & 3) << 3;
            long g = (long)(col0 + n) * K + k0 + c8;
            *(float4*)&sBH[n * BSTT + c8] = *(const float4*)(pBH + g);
            *(float4*)&sBL[n * BSTT + c8] = *(const float4*)(pBL + g);
        } else {
            // B is [K,N] row-major; tile [BK rows x BN cols], row stride BSTN
            int kk = tid >> 3;
            int c8 = (tid & 7) << 3;
            long g = (long)(k0 + kk) * N + col0 + c8;
            *(float4*)&sBH[kk * BSTN + c8] = *(const float4*)(pBH + g);
            *(float4*)&sBL[kk * BSTN + c8] = *(const float4*)(pBL + g);
        }
        __syncthreads();

        for (int kk = 0; kk < BK; kk += 16) {
            wmma::fragment<wmma::matrix_a, 16, 16, 16, bf16, wmma::row_major> aH[2], aL[2];
            for (int i = 0; i < 2; i++) {
                const bf16* pa = &sAH[(wm * 32 + i * 16) * AST + kk];
                const bf16* pl = &sAL[(wm * 32 + i * 16) * AST + kk];
                wmma::load_matrix_sync(aH[i], pa, AST);
                wmma::load_matrix_sync(aL[i], pl, AST);
            }
            if (TB) {
                wmma::fragment<wmma::matrix_b, 16, 16, 16, bf16, wmma::col_major> bH[2], bL[2];
                for (int j = 0; j < 2; j++) {
                    const bf16* pb = &sBH[(wn * 32 + j * 16) * BSTT + kk];
                    const bf16* pl = &sBL[(wn * 32 + j * 16) * BSTT + kk];
                    wmma::load_matrix_sync(bH[j], pb, BSTT);
                    wmma::load_matrix_sync(bL[j], pl, BSTT);
                }
                for (int i = 0; i < 2; i++)
                    for (int j = 0; j < 2; j++) {
                        wmma::mma_sync(acc[i][j], aH[i], bH[j], acc[i][j]);
                        wmma::mma_sync(acc[i][j], aH[i], bL[j], acc[i][j]);
                        wmma::mma_sync(acc[i][j], aL[i], bH[j], acc[i][j]);
                    }
            } else {
                wmma::fragment<wmma::matrix_b, 16, 16, 16, bf16, wmma::row_major> bH[2], bL[2];
                for (int j = 0; j < 2; j++) {
                    const bf16* pb = &sBH[kk * BSTN + wn * 32 + j * 16];
                    const bf16* pl = &sBL[kk * BSTN + wn * 32 + j * 16];
                    wmma::load_matrix_sync(bH[j], pb, BSTN);
                    wmma::load_matrix_sync(bL[j], pl, BSTN);
                }
                for (int i = 0; i < 2; i++)
                    for (int j = 0; j < 2; j++) {
                        wmma::mma_sync(acc[i][j], aH[i], bH[j], acc[i][j]);
                        wmma::mma_sync(acc[i][j], aH[i], bL[j], acc[i][j]);
                        wmma::mma_sync(acc[i][j], aL[i], bH[j], acc[i][j]);
                    }
            }
        }
        __syncthreads();
    }

    for (int i = 0; i < 2; i++)
        for (int j = 0; j < 2; j++) {
            int r = row0 + wm * 32 + i * 16;
            int c = col0 + wn * 32 + j * 16;
            wmma::store_matrix_sync(pC + (long)r * N + c, acc[i][j], N, wmma::mem_row_major);
        }
}

__global__ void __launch_bounds__(256) split_k(const float* __restrict__ s,
                                               bf16* __restrict__ h, bf16* __restrict__ l, long n)
{
    long i = (long)blockIdx.x * 256 + threadIdx.x;
    if (i < n) {
        bf16 hi, lo;
        split2(s[i], hi, lo);
        h[i] = hi;
        l[i] = lo;
    }
}

// softmax over fp32 logits, scale 1/8, writes bf16 hi/lo probabilities
__global__ void __launch_bounds__(256) softmax_k(const float* __restrict__ scF,
                                                 bf16* __restrict__ scH, bf16* __restrict__ scL)
{
    __shared__ float red[8];
    const float* pF = scF + (long)blockIdx.x * SQ;
    bf16* pH = scH + (long)blockIdx.x * SQ;
    bf16* pL = scL + (long)blockIdx.x * SQ;
    int tid = threadIdx.x;
    float x[4];
    for (int j = 0; j < 4; j++) x[j] = pF[tid + j * 256] * 0.125f;
    float m = fmaxf(fmaxf(x[0], x[1]), fmaxf(x[2], x[3]));
    for (int o = 16; o; o >>= 1) m = fmaxf(m, __shfl_xor_sync(0xffffffffu, m, o));
    if ((tid & 31) == 0) red[tid >> 5] = m;
    __syncthreads();
    for (int w = 0; w < 8; w++) m = fmaxf(m, red[w]);
    float s = 0.f;
    for (int j = 0; j < 4; j++) {
        x[j] = expf(x[j] - m);
        s += x[j];
    }
    for (int o = 16; o; o >>= 1) s += __shfl_xor_sync(0xffffffffu, s, o);
    __syncthreads();
    if ((tid & 31) == 0) red[tid >> 5] = s;
    __syncthreads();
    s = 0.f;
    for (int w = 0; w < 8; w++) s += red[w];
    float inv = 1.f / s;
    for (int j = 0; j < 4; j++) {
        int c = tid + j * 256;
        bf16 hi, lo;
        split2(x[j] * inv, hi, lo);
        pH[c] = hi;
        pL[c] = lo;
    }
}

__global__ void __launch_bounds__(256) resid_reduce_k(
    float* __restrict__ net, const float* __restrict__ add,
    float* __restrict__ stats, int relu)
{
    int h = blockIdx.y;
    int chunk = blockIdx.x;
    int c = threadIdx.x;
    long base = ((long)h * RR + (long)chunk * 64) * NV + c;
    float s = 0.f;
    float s2 = 0.f;
    for (int r = 0; r < 64; r++) {
        long idx = base + (long)r * NV;
        float a = add[idx];
        if (relu) a = fmaxf(a, 0.f);
        float val = net[idx] + a;
        net[idx] = val;
        s += val;
        s2 += val * val;
    }
    atomicAdd(&stats[h * NV + c], s);
    atomicAdd(&stats[NH * NV + h * NV + c], s2);
}

__global__ void __launch_bounds__(256) bn_apply_k(
    float* __restrict__ net, bf16* __restrict__ netH, bf16* __restrict__ netL,
    const float* __restrict__ stats,
    const float* __restrict__ gamma, const float* __restrict__ beta, int t)
{
    long idx = (long)blockIdx.x * 256 + threadIdx.x;
    int c = (int)(idx & (NV - 1));
    int h = (int)(idx >> 20);
    float mean = stats[h * NV + c] * (1.f / RR);
    float ex2  = stats[NH * NV + h * NV + c] * (1.f / RR);
    float var  = ex2 - mean * mean;
    float g = gamma[(h * NT + t) * NV + c];
    float b = beta [(h * NT + t) * NV + c];
    float val = (net[idx] - mean) * rsqrtf(var + EPSBN) * g + b;
    net[idx] = val;
    bf16 hi, lo;
    split2(val, hi, lo);
    netH[idx] = hi;
    netL[idx] = lo;
}

__global__ void __launch_bounds__(256) bcast_k(
    float* __restrict__ net, bf16* __restrict__ netH, bf16* __restrict__ netL,
    const float* __restrict__ net0)
{
    long idx = (long)blockIdx.x * 256 + threadIdx.x;
    float v = net0[idx];
    bf16 hi, lo;
    split2(v, hi, lo);
    for (int h = 0; h < NH; h++) {
        long o = (long)h * RR * NV + idx;
        net[o] = v;
        netH[o] = hi;
        netL[o] = lo;
    }
}

__global__ void __launch_bounds__(256) final_k(float* __restrict__ out,
                                               const float* __restrict__ net)
{
    long idx = (long)blockIdx.x * 256 + threadIdx.x;
    int c = (int)(idx & (NV - 1));
    int h = (int)((idx >> 8) & (NH - 1));
    long bs = idx >> 11;
    out[idx] = net[((long)h * RR + bs) * NV + c];
}

extern "C" void kernel_launch(void* const* d_in, const int* in_sizes, int n_in,
                              void* d_out, int out_size)
{
    (void)in_sizes;
    (void)n_in;
    (void)out_size;
    const float* x    = (const float*)d_in[0];
    const float* W_in = (const float*)d_in[1];
    const float* Wq   = (const float*)d_in[2];
    const float* Wk   = (const float*)d_in[3];
    const float* Wv   = (const float*)d_in[4];
    const float* Wd   = (const float*)d_in[5];
    const float* g1   = (const float*)d_in[6];
    const float* b1   = (const float*)d_in[7];
    const float* g2   = (const float*)d_in[8];
    const float* b2   = (const float*)d_in[9];
    float* out = (float*)d_out;

    float* net;
    float* net0;
    float* tmp;
    float* stats;
    float* scF;
    float* qF;
    float* kF;
    float* vF;
    bf16* netH;
    bf16* netL;
    bf16* qH;
    bf16* qL;
    bf16* kH;
    bf16* kL;
    bf16* vH;
    bf16* vL;
    bf16* scH;
    bf16* scL;
    bf16* xH;
    bf16* xL;
    bf16* WinH;
    bf16* WinL;
    bf16* WqH;
    bf16* WqL;
    bf16* WkH;
    bf16* WkL;
    bf16* WvH;
    bf16* WvL;
    bf16* WdH;
    bf16* WdL;
    cudaGetSymbolAddress((void**)&net,  g_net);
    cudaGetSymbolAddress((void**)&net0, g_net0);
    cudaGetSymbolAddress((void**)&tmp,  g_tmp);
    cudaGetSymbolAddress((void**)&stats, g_stats);
    cudaGetSymbolAddress((void**)&scF,  g_scF);
    cudaGetSymbolAddress((void**)&qF,   g_qF);
    cudaGetSymbolAddress((void**)&kF,   g_kF);
    cudaGetSymbolAddress((void**)&vF,   g_vF);
    cudaGetSymbolAddress((void**)&netH, g_netH);
    cudaGetSymbolAddress((void**)&netL, g_netL);
    cudaGetSymbolAddress((void**)&qH,   g_qH);
    cudaGetSymbolAddress((void**)&qL,   g_qL);
    cudaGetSymbolAddress((void**)&kH,   g_kH);
    cudaGetSymbolAddress((void**)&kL,   g_kL);
    cudaGetSymbolAddress((void**)&vH,   g_vH);
    cudaGetSymbolAddress((void**)&vL,   g_vL);
    cudaGetSymbolAddress((void**)&scH,  g_scH);
    cudaGetSymbolAddress((void**)&scL,  g_scL);
    cudaGetSymbolAddress((void**)&xH,   g_xH);
    cudaGetSymbolAddress((void**)&xL,   g_xL);
    cudaGetSymbolAddress((void**)&WinH, g_WinH);
    cudaGetSymbolAddress((void**)&WinL, g_WinL);
    cudaGetSymbolAddress((void**)&WqH,  g_WqH);
    cudaGetSymbolAddress((void**)&WqL,  g_WqL);
    cudaGetSymbolAddress((void**)&WkH,  g_WkH);
    cudaGetSymbolAddress((void**)&WkL,  g_WkL);
    cudaGetSymbolAddress((void**)&WvH,  g_WvH);
    cudaGetSymbolAddress((void**)&WvL,  g_WvL);
    cudaGetSymbolAddress((void**)&WdH,  g_WdH);
    cudaGetSymbolAddress((void**)&WdL,  g_WdL);

    const long RV = (long)RR * NV;
    const long RK = (long)RR * NKD;
    const long SS = (long)SQ * SQ;
    const long WQK = (long)NV * NKD;
    const long WVV = (long)NV * NV;

    split_k<<<(int)(RV / 256), 256>>>(x, xH, xL, RV);
    split_k<<<(int)(WVV / 256), 256>>>(W_in, WinH, WinL, WVV);
    split_k<<<(int)((NH * NT * WQK) / 256), 256>>>(Wq, WqH, WqL, NH * NT * WQK);
    split_k<<<(int)((NH * NT * WQK) / 256), 256>>>(Wk, WkH, WkL, NH * NT * WQK);
    split_k<<<(int)((NH * NT * WVV) / 256), 256>>>(Wv, WvH, WvL, NH * NT * WVV);
    split_k<<<(int)((NH * NT * WVV) / 256), 256>>>(Wd, WdH, WdL, NH * NT * WVV);

    gemmW_k<0><<<dim3(NV / BN, RR / BM, 1), 256>>>(
        xH, xL, WinH, WinL, net0, RR, NV, 256, 0, 0, 0);
    bcast_k<<<(int)(RV / 256), 256>>>(net, netH, netL, net0);

    for (int t = 0; t < NT; t++) {
        gemmW_k<0><<<dim3(NKD / BN, RR / BM, NH), 256>>>(
            netH, netL, WqH + (long)t * WQK, WqL + (long)t * WQK,
            qF, RR, NKD, NV, RV, (long)NT * WQK, RK);
        split_k<<<(int)((NH * RK) / 256), 256>>>(qF, qH, qL, NH * RK);
        gemmW_k<0><<<dim3(NKD / BN, RR / BM, NH), 256>>>(
            netH, netL, WkH + (long)t * WQK, WkL + (long)t * WQK,
            kF, RR, NKD, NV, RV, (long)NT * WQK, RK);
        split_k<<<(int)((NH * RK) / 256), 256>>>(kF, kH, kL, NH * RK);
        gemmW_k<0><<<dim3(NV / BN, RR / BM, NH), 256>>>(
            netH, netL, WvH + (long)t * WVV, WvL + (long)t * WVV,
            vF, RR, NV, NV, RV, (long)NT * WVV, RV);
        split_k<<<(int)((NH * RV) / 256), 256>>>(vF, vH, vL, NH * RV);

        gemmW_k<1><<<dim3(SQ / BN, SQ / BM, NZ), 256>>>(
            qH, qL, kH, kL, scF,
            SQ, SQ, NKD, (long)SQ * NKD, (long)SQ * NKD, SS);
        softmax_k<<<NZ * SQ, 256>>>(scF, scH, scL);
        gemmW_k<0><<<dim3(NV / BN, SQ / BM, NZ), 256>>>(
            scH, scL, vH, vL, tmp,
            SQ, NV, SQ, SS, (long)SQ * NV, (long)SQ * NV);

        cudaMemsetAsync(stats, 0, sizeof(float) * 2 * NH * NV);
        resid_reduce_k<<<dim3(RR / 64, NH), 256>>>(net, tmp, stats, 0);
        bn_apply_k<<<(int)((NH * RV) / 256), 256>>>(net, netH, netL, stats, g1, b1, t);

        gemmW_k<0><<<dim3(NV / BN, RR / BM, NH), 256>>>(
            netH, netL, WdH + (long)t * WVV, WdL + (long)t * WVV,
            tmp, RR, NV, NV, RV, (long)NT * WVV, RV);

        cudaMemsetAsync(stats, 0, sizeof(float) * 2 * NH * NV);
        resid_reduce_k<<<dim3(RR / 64, NH), 256>>>(net, tmp, stats, 1);
        bn_apply_k<<<(int)((NH * RV) / 256), 256>>>(net, netH, netL, stats, g2, b2, t);
    }

    final_k<<<(int)(((long)NB * SQ * NH * NV) / 256), 256>>>(out, net);
}

// round 10
// speedup vs baseline: 1.5226x; 1.1987x over previous
#include <cuda_runtime.h>
#include <cuda_bf16.h>
#include <cuda_pipeline.h>
#include <mma.h>
#include <cstdint>

using namespace nvcuda;

#define NH   8
#define NT   4
#define NB   4
#define SQ   1024
#define NV   256
#define NKD  64
#define RR   4096
#define NZ   32
#define EPSBN 1e-3f

typedef __nv_bfloat16 bf16;

__device__ float g_net [(long)NH*RR*NV];
__device__ float g_net0[(long)RR*NV];
__device__ float g_tmp [(long)NH*RR*NV];
__device__ float g_stats[2*NH*NV];

__device__ bf16 g_netH[(long)NH*RR*NV];
__device__ bf16 g_netL[(long)NH*RR*NV];
__device__ bf16 g_qH[(long)NH*RR*NKD];
__device__ bf16 g_qL[(long)NH*RR*NKD];
__device__ bf16 g_kH[(long)NH*RR*NKD];
__device__ bf16 g_kL[(long)NH*RR*NKD];
__device__ bf16 g_vH[(long)NH*RR*NV];
__device__ bf16 g_vL[(long)NH*RR*NV];
__device__ bf16 g_scH[(long)NZ*SQ*SQ];
__device__ bf16 g_scL[(long)NZ*SQ*SQ];
__device__ bf16 g_xH[(long)RR*256];
__device__ bf16 g_xL[(long)RR*256];
__device__ bf16 g_WinH[256*NV];
__device__ bf16 g_WinL[256*NV];
__device__ bf16 g_WqH[NH*NT*NV*NKD];
__device__ bf16 g_WqL[NH*NT*NV*NKD];
__device__ bf16 g_WkH[NH*NT*NV*NKD];
__device__ bf16 g_WkL[NH*NT*NV*NKD];
__device__ bf16 g_WvH[NH*NT*NV*NV];
__device__ bf16 g_WvL[NH*NT*NV*NV];
__device__ bf16 g_WdH[NH*NT*NV*NV];
__device__ bf16 g_WdL[NH*NT*NV*NV];

__device__ __forceinline__ void split2(float v, bf16& h, bf16& l) {
    h = __float2bfloat16(v);
    l = __float2bfloat16(v - __bfloat162float(h));
}

// bf16x3 GEMM via wmma with 2-stage cp.async pipeline.
// C = A times B (TB=0) or A times B-transpose (TB=1).
// A: [M,K] row-major hi/lo bf16. B: [K,N] row-major (TB=0) or [N,K] row-major (TB=1).
// Output: fp32 C (SPLIT=0) or hi/lo bf16 pair (SPLIT=1).
// Block tile 128x64x32, 256 threads = 8 warps (4 along M, 2 along N),
// warp tile 32x32 = 2x2 wmma 16x16x16 fragments, 3 MMAs per fragment pair.
#define BM 128
#define BN 64
#define BK 32
#define AST 48
#define BSTN 80
#define BSTT 48

// dynamic smem layout per stage (bytes): AH 12288, AL 12288, BH 6144, BL 6144
#define OFF_AL 12288
#define OFF_BH 24576
#define OFF_BL 30720
#define STAGE_BYTES 36864
#define SMEM_TOTAL 73728

template<int TB, int SPLIT>
__global__ void __launch_bounds__(256) gemmW_k(
    const bf16* __restrict__ AH, const bf16* __restrict__ AL,
    const bf16* __restrict__ BH, const bf16* __restrict__ BL,
    float* __restrict__ CF, bf16* __restrict__ CH, bf16* __restrict__ CL,
    int M, int N, int K, long sA, long sB, long sC)
{
    extern __shared__ char dsm[];

    const bf16* pAH = AH + (long)blockIdx.z * sA;
    const bf16* pAL = AL + (long)blockIdx.z * sA;
    const bf16* pBH = BH + (long)blockIdx.z * sB;
    const bf16* pBL = BL + (long)blockIdx.z * sB;

    int tid = threadIdx.x;
    int row0 = blockIdx.y * BM;
    int col0 = blockIdx.x * BN;
    int warp = tid >> 5;
    int lane = tid & 31;
    int wm = warp & 3;
    int wn = warp >> 2;

    wmma::fragment<wmma::accumulator, 16, 16, 16, float> acc[2][2];
    for (int i = 0; i < 2; i++)
        for (int j = 0; j < 2; j++)
            wmma::fill_fragment(acc[i][j], 0.0f);

    int nit = K / BK;

    // async load of one stage
    auto load_stage = [&](int it, int st) {
        char* base = dsm + st * STAGE_BYTES;
        bf16* sAH = (bf16*)(base);
        bf16* sAL = (bf16*)(base + OFF_AL);
        bf16* sBH = (bf16*)(base + OFF_BH);
        bf16* sBL = (bf16*)(base + OFF_BL);
        int k0 = it * BK;
        // A tile 128x32, two rounds of 256 x 16B per array
        for (int l = 0; l < 2; l++) {
            int lin = tid + l * 256;
            int r = lin >> 2;
            int c8 = (lin & 3) << 3;
            long g = (long)(row0 + r) * K + k0 + c8;
            __pipeline_memcpy_async(&sAH[r * AST + c8], pAH + g, 16);
            __pipeline_memcpy_async(&sAL[r * AST + c8], pAL + g, 16);
        }
        if (TB) {
            // tile [BN=64 rows x BK=32 cols], row stride BSTT
            int n = tid >> 2;
            int c8 = (tid & 3) << 3;
            long g = (long)(col0 + n) * K + k0 + c8;
            __pipeline_memcpy_async(&sBH[n * BSTT + c8], pBH + g, 16);
            __pipeline_memcpy_async(&sBL[n * BSTT + c8], pBL + g, 16);
        } else {
            // tile [BK=32 rows x BN=64 cols], row stride BSTN
            int kk = tid >> 3;
            int c8 = (tid & 7) << 3;
            long g = (long)(k0 + kk) * N + col0 + c8;
            __pipeline_memcpy_async(&sBH[kk * BSTN + c8], pBH + g, 16);
            __pipeline_memcpy_async(&sBL[kk * BSTN + c8], pBL + g, 16);
        }
    };

    load_stage(0, 0);
    __pipeline_commit();

    for (int it = 0; it < nit; it++) {
        if (it + 1 < nit) {
            load_stage(it + 1, (it + 1) & 1);
            __pipeline_commit();
            __pipeline_wait_prior(1);
        } else {
            __pipeline_wait_prior(0);
        }
        __syncthreads();

        char* base = dsm + (it & 1) * STAGE_BYTES;
        bf16* sAH = (bf16*)(base);
        bf16* sAL = (bf16*)(base + OFF_AL);
        bf16* sBH = (bf16*)(base + OFF_BH);
        bf16* sBL = (bf16*)(base + OFF_BL);

        for (int kk = 0; kk < BK; kk += 16) {
            wmma::fragment<wmma::matrix_a, 16, 16, 16, bf16, wmma::row_major> aH[2], aL[2];
            for (int i = 0; i < 2; i++) {
                wmma::load_matrix_sync(aH[i], &sAH[(wm * 32 + i * 16) * AST + kk], AST);
                wmma::load_matrix_sync(aL[i], &sAL[(wm * 32 + i * 16) * AST + kk], AST);
            }
            if (TB) {
                wmma::fragment<wmma::matrix_b, 16, 16, 16, bf16, wmma::col_major> bH[2], bL[2];
                for (int j = 0; j < 2; j++) {
                    wmma::load_matrix_sync(bH[j], &sBH[(wn * 32 + j * 16) * BSTT + kk], BSTT);
                    wmma::load_matrix_sync(bL[j], &sBL[(wn * 32 + j * 16) * BSTT + kk], BSTT);
                }
                for (int i = 0; i < 2; i++)
                    for (int j = 0; j < 2; j++) {
                        wmma::mma_sync(acc[i][j], aH[i], bH[j], acc[i][j]);
                        wmma::mma_sync(acc[i][j], aH[i], bL[j], acc[i][j]);
                        wmma::mma_sync(acc[i][j], aL[i], bH[j], acc[i][j]);
                    }
            } else {
                wmma::fragment<wmma::matrix_b, 16, 16, 16, bf16, wmma::row_major> bH[2], bL[2];
                for (int j = 0; j < 2; j++) {
                    wmma::load_matrix_sync(bH[j], &sBH[kk * BSTN + wn * 32 + j * 16], BSTN);
                    wmma::load_matrix_sync(bL[j], &sBL[kk * BSTN + wn * 32 + j * 16], BSTN);
                }
                for (int i = 0; i < 2; i++)
                    for (int j = 0; j < 2; j++) {
                        wmma::mma_sync(acc[i][j], aH[i], bH[j], acc[i][j]);
                        wmma::mma_sync(acc[i][j], aH[i], bL[j], acc[i][j]);
                        wmma::mma_sync(acc[i][j], aL[i], bH[j], acc[i][j]);
                    }
            }
        }
        __syncthreads();
    }

    if (SPLIT) {
        // stage accumulators through smem, write hi/lo bf16 pair
        float* st = (float*)dsm + warp * 1024;
        for (int i = 0; i < 2; i++)
            for (int j = 0; j < 2; j++)
                wmma::store_matrix_sync(st + (i * 16) * 32 + j * 16, acc[i][j], 32,
                                        wmma::mem_row_major);
        __syncwarp();
        bf16* pCH = CH + (long)blockIdx.z * sC;
        bf16* pCL = CL + (long)blockIdx.z * sC;
        for (int r = 0; r < 32; r++) {
            float v = st[r * 32 + lane];
            bf16 hi, lo;
            split2(v, hi, lo);
            long off = (long)(row0 + wm * 32 + r) * N + col0 + wn * 32 + lane;
            pCH[off] = hi;
            pCL[off] = lo;
        }
    } else {
        float* pC = CF + (long)blockIdx.z * sC;
        for (int i = 0; i < 2; i++)
            for (int j = 0; j < 2; j++) {
                int r = row0 + wm * 32 + i * 16;
                int c = col0 + wn * 32 + j * 16;
                wmma::store_matrix_sync(pC + (long)r * N + c, acc[i][j], N,
                                        wmma::mem_row_major);
            }
    }
}

__global__ void __launch_bounds__(256) split_k(const float* __restrict__ s,
                                               bf16* __restrict__ h, bf16* __restrict__ l, long n)
{
    long i = (long)blockIdx.x * 256 + threadIdx.x;
    if (i < n) {
        bf16 hi, lo;
        split2(s[i], hi, lo);
        h[i] = hi;
        l[i] = lo;
    }
}

// softmax over hi/lo bf16 logits in place, scale 1/8
__global__ void __launch_bounds__(256) softmax_k(bf16* __restrict__ scH, bf16* __restrict__ scL)
{
    __shared__ float red[8];
    bf16* pH = scH + (long)blockIdx.x * SQ;
    bf16* pL = scL + (long)blockIdx.x * SQ;
    int tid = threadIdx.x;
    float x[4];
    for (int j = 0; j < 4; j++) {
        int c = tid + j * 256;
        x[j] = (__bfloat162float(pH[c]) + __bfloat162float(pL[c])) * 0.125f;
    }
    float m = fmaxf(fmaxf(x[0], x[1]), fmaxf(x[2], x[3]));
    for (int o = 16; o; o >>= 1) m = fmaxf(m, __shfl_xor_sync(0xffffffffu, m, o));
    if ((tid & 31) == 0) red[tid >> 5] = m;
    __syncthreads();
    for (int w = 0; w < 8; w++) m = fmaxf(m, red[w]);
    float s = 0.f;
    for (int j = 0; j < 4; j++) {
        x[j] = expf(x[j] - m);
        s += x[j];
    }
    for (int o = 16; o; o >>= 1) s += __shfl_xor_sync(0xffffffffu, s, o);
    __syncthreads();
    if ((tid & 31) == 0) red[tid >> 5] = s;
    __syncthreads();
    s = 0.f;
    for (int w = 0; w < 8; w++) s += red[w];
    float inv = 1.f / s;
    for (int j = 0; j < 4; j++) {
        int c = tid + j * 256;
        bf16 hi, lo;
        split2(x[j] * inv, hi, lo);
        pH[c] = hi;
        pL[c] = lo;
    }
}

__global__ void __launch_bounds__(256) resid_reduce_k(
    float* __restrict__ net, const float* __restrict__ add,
    float* __restrict__ stats, int relu)
{
    int h = blockIdx.y;
    int chunk = blockIdx.x;
    int c = threadIdx.x;
    long base = ((long)h * RR + (long)chunk * 64) * NV + c;
    float s = 0.f;
    float s2 = 0.f;
    for (int r = 0; r < 64; r++) {
        long idx = base + (long)r * NV;
        float a = add[idx];
        if (relu) a = fmaxf(a, 0.f);
        float val = net[idx] + a;
        net[idx] = val;
        s += val;
        s2 += val * val;
    }
    atomicAdd(&stats[h * NV + c], s);
    atomicAdd(&stats[NH * NV + h * NV + c], s2);
}

__global__ void __launch_bounds__(256) bn_apply_k(
    float* __restrict__ net, bf16* __restrict__ netH, bf16* __restrict__ netL,
    const float* __restrict__ stats,
    const float* __restrict__ gamma, const float* __restrict__ beta, int t)
{
    long idx = (long)blockIdx.x * 256 + threadIdx.x;
    int c = (int)(idx & (NV - 1));
    int h = (int)(idx >> 20);
    float mean = stats[h * NV + c] * (1.f / RR);
    float ex2  = stats[NH * NV + h * NV + c] * (1.f / RR);
    float var  = ex2 - mean * mean;
    float g = gamma[(h * NT + t) * NV + c];
    float b = beta [(h * NT + t) * NV + c];
    float val = (net[idx] - mean) * rsqrtf(var + EPSBN) * g + b;
    net[idx] = val;
    bf16 hi, lo;
    split2(val, hi, lo);
    netH[idx] = hi;
    netL[idx] = lo;
}

__global__ void __launch_bounds__(256) bcast_k(
    float* __restrict__ net, bf16* __restrict__ netH, bf16* __restrict__ netL,
    const float* __restrict__ net0)
{
    long idx = (long)blockIdx.x * 256 + threadIdx.x;
    float v = net0[idx];
    bf16 hi, lo;
    split2(v, hi, lo);
    for (int h = 0; h < NH; h++) {
        long o = (long)h * RR * NV + idx;
        net[o] = v;
        netH[o] = hi;
        netL[o] = lo;
    }
}

__global__ void __launch_bounds__(256) final_k(float* __restrict__ out,
                                               const float* __restrict__ net)
{
    long idx = (long)blockIdx.x * 256 + threadIdx.x;
    int c = (int)(idx & (NV - 1));
    int h = (int)((idx >> 8) & (NH - 1));
    long bs = idx >> 11;
    out[idx] = net[((long)h * RR + bs) * NV + c];
}

extern "C" void kernel_launch(void* const* d_in, const int* in_sizes, int n_in,
                              void* d_out, int out_size)
{
    (void)in_sizes;
    (void)n_in;
    (void)out_size;
    const float* x    = (const float*)d_in[0];
    const float* W_in = (const float*)d_in[1];
    const float* Wq   = (const float*)d_in[2];
    const float* Wk   = (const float*)d_in[3];
    const float* Wv   = (const float*)d_in[4];
    const float* Wd   = (const float*)d_in[5];
    const float* g1   = (const float*)d_in[6];
    const float* b1   = (const float*)d_in[7];
    const float* g2   = (const float*)d_in[8];
    const float* b2   = (const float*)d_in[9];
    float* out = (float*)d_out;

    float* net;
    float* net0;
    float* tmp;
    float* stats;
    bf16* netH;
    bf16* netL;
    bf16* qH;
    bf16* qL;
    bf16* kH;
    bf16* kL;
    bf16* vH;
    bf16* vL;
    bf16* scH;
    bf16* scL;
    bf16* xH;
    bf16* xL;
    bf16* WinH;
    bf16* WinL;
    bf16* WqH;
    bf16* WqL;
    bf16* WkH;
    bf16* WkL;
    bf16* WvH;
    bf16* WvL;
    bf16* WdH;
    bf16* WdL;
    cudaGetSymbolAddress((void**)&net,  g_net);
    cudaGetSymbolAddress((void**)&net0, g_net0);
    cudaGetSymbolAddress((void**)&tmp,  g_tmp);
    cudaGetSymbolAddress((void**)&stats, g_stats);
    cudaGetSymbolAddress((void**)&netH, g_netH);
    cudaGetSymbolAddress((void**)&netL, g_netL);
    cudaGetSymbolAddress((void**)&qH,   g_qH);
    cudaGetSymbolAddress((void**)&qL,   g_qL);
    cudaGetSymbolAddress((void**)&kH,   g_kH);
    cudaGetSymbolAddress((void**)&kL,   g_kL);
    cudaGetSymbolAddress((void**)&vH,   g_vH);
    cudaGetSymbolAddress((void**)&vL,   g_vL);
    cudaGetSymbolAddress((void**)&scH,  g_scH);
    cudaGetSymbolAddress((void**)&scL,  g_scL);
    cudaGetSymbolAddress((void**)&xH,   g_xH);
    cudaGetSymbolAddress((void**)&xL,   g_xL);
    cudaGetSymbolAddress((void**)&WinH, g_WinH);
    cudaGetSymbolAddress((void**)&WinL, g_WinL);
    cudaGetSymbolAddress((void**)&WqH,  g_WqH);
    cudaGetSymbolAddress((void**)&WqL,  g_WqL);
    cudaGetSymbolAddress((void**)&WkH,  g_WkH);
    cudaGetSymbolAddress((void**)&WkL,  g_WkL);
    cudaGetSymbolAddress((void**)&WvH,  g_WvH);
    cudaGetSymbolAddress((void**)&WvL,  g_WvL);
    cudaGetSymbolAddress((void**)&WdH,  g_WdH);
    cudaGetSymbolAddress((void**)&WdL,  g_WdL);

    cudaFuncSetAttribute(gemmW_k<0, 0>, cudaFuncAttributeMaxDynamicSharedMemorySize, SMEM_TOTAL);
    cudaFuncSetAttribute(gemmW_k<0, 1>, cudaFuncAttributeMaxDynamicSharedMemorySize, SMEM_TOTAL);
    cudaFuncSetAttribute(gemmW_k<1, 1>, cudaFuncAttributeMaxDynamicSharedMemorySize, SMEM_TOTAL);

    const long RV = (long)RR * NV;
    const long RK = (long)RR * NKD;
    const long SS = (long)SQ * SQ;
    const long WQK = (long)NV * NKD;
    const long WVV = (long)NV * NV;

    split_k<<<(int)(RV / 256), 256>>>(x, xH, xL, RV);
    split_k<<<(int)(WVV / 256), 256>>>(W_in, WinH, WinL, WVV);
    split_k<<<(int)((NH * NT * WQK) / 256), 256>>>(Wq, WqH, WqL, NH * NT * WQK);
    split_k<<<(int)((NH * NT * WQK) / 256), 256>>>(Wk, WkH, WkL, NH * NT * WQK);
    split_k<<<(int)((NH * NT * WVV) / 256), 256>>>(Wv, WvH, WvL, NH * NT * WVV);
    split_k<<<(int)((NH * NT * WVV) / 256), 256>>>(Wd, WdH, WdL, NH * NT * WVV);

    gemmW_k<0, 0><<<dim3(NV / BN, RR / BM, 1), 256, SMEM_TOTAL>>>(
        xH, xL, WinH, WinL, net0, (bf16*)0, (bf16*)0, RR, NV, 256, 0, 0, 0);
    bcast_k<<<(int)(RV / 256), 256>>>(net, netH, netL, net0);

    for (int t = 0; t < NT; t++) {
        gemmW_k<0, 1><<<dim3(NKD / BN, RR / BM, NH), 256, SMEM_TOTAL>>>(
            netH, netL, WqH + (long)t * WQK, WqL + (long)t * WQK,
            (float*)0, qH, qL, RR, NKD, NV, RV, (long)NT * WQK, RK);
        gemmW_k<0, 1><<<dim3(NKD / BN, RR / BM, NH), 256, SMEM_TOTAL>>>(
            netH, netL, WkH + (long)t * WQK, WkL + (long)t * WQK,
            (float*)0, kH, kL, RR, NKD, NV, RV, (long)NT * WQK, RK);
        gemmW_k<0, 1><<<dim3(NV / BN, RR / BM, NH), 256, SMEM_TOTAL>>>(
            netH, netL, WvH + (long)t * WVV, WvL + (long)t * WVV,
            (float*)0, vH, vL, RR, NV, NV, RV, (long)NT * WVV, RV);

        gemmW_k<1, 1><<<dim3(SQ / BN, SQ / BM, NZ), 256, SMEM_TOTAL>>>(
            qH, qL, kH, kL, (float*)0, scH, scL,
            SQ, SQ, NKD, (long)SQ * NKD, (long)SQ * NKD, SS);
        softmax_k<<<NZ * SQ, 256>>>(scH, scL);
        gemmW_k<0, 0><<<dim3(NV / BN, SQ / BM, NZ), 256, SMEM_TOTAL>>>(
            scH, scL, vH, vL, tmp, (bf16*)0, (bf16*)0,
            SQ, NV, SQ, SS, (long)SQ * NV, (long)SQ * NV);

        cudaMemsetAsync(stats, 0, sizeof(float) * 2 * NH * NV);
        resid_reduce_k<<<dim3(RR / 64, NH), 256>>>(net, tmp, stats, 0);
        bn_apply_k<<<(int)((NH * RV) / 256), 256>>>(net, netH, netL, stats, g1, b1, t);

        gemmW_k<0, 0><<<dim3(NV / BN, RR / BM, NH), 256, SMEM_TOTAL>>>(
            netH, netL, WdH + (long)t * WVV, WdL + (long)t * WVV,
            tmp, (bf16*)0, (bf16*)0, RR, NV, NV, RV, (long)NT * WVV, RV);

        cudaMemsetAsync(stats, 0, sizeof(float) * 2 * NH * NV);
        resid_reduce_k<<<dim3(RR / 64, NH), 256>>>(net, tmp, stats, 1);
        bn_apply_k<<<(int)((NH * RV) / 256), 256>>>(net, netH, netL, stats, g2, b2, t);
    }

    final_k<<<(int)(((long)NB * SQ * NH * NV) / 256), 256>>>(out, net);
}

// round 12
// speedup vs baseline: 1.6139x; 1.0600x over previous
#include <cuda_runtime.h>
#include <cuda_bf16.h>
#include <cuda_pipeline.h>
#include <mma.h>
#include <cstdint>

using namespace nvcuda;

#define NH   8
#define NT   4
#define NB   4
#define SQ   1024
#define NV   256
#define NKD  64
#define RR   4096
#define NZ   32
#define EPSBN 1e-3f

typedef __nv_bfloat16 bf16;

__device__ float g_net [(long)NH*RR*NV];
__device__ float g_net0[(long)RR*NV];
__device__ float g_tmp [(long)NH*RR*NV];
__device__ float g_stats[2*NH*NV];

__device__ bf16 g_netH[(long)NH*RR*NV];
__device__ bf16 g_netL[(long)NH*RR*NV];
__device__ bf16 g_qH[(long)NH*RR*NKD];
__device__ bf16 g_qL[(long)NH*RR*NKD];
__device__ bf16 g_kH[(long)NH*RR*NKD];
__device__ bf16 g_kL[(long)NH*RR*NKD];
__device__ bf16 g_vH[(long)NH*RR*NV];
__device__ bf16 g_vL[(long)NH*RR*NV];
__device__ bf16 g_scH[(long)NZ*SQ*SQ];
__device__ bf16 g_scL[(long)NZ*SQ*SQ];
__device__ bf16 g_xH[(long)RR*256];
__device__ bf16 g_xL[(long)RR*256];
__device__ bf16 g_WinH[256*NV];
__device__ bf16 g_WinL[256*NV];
__device__ bf16 g_WqH[NH*NT*NV*NKD];
__device__ bf16 g_WqL[NH*NT*NV*NKD];
__device__ bf16 g_WkH[NH*NT*NV*NKD];
__device__ bf16 g_WkL[NH*NT*NV*NKD];
__device__ bf16 g_WvH[NH*NT*NV*NV];
__device__ bf16 g_WvL[NH*NT*NV*NV];
__device__ bf16 g_WdH[NH*NT*NV*NV];
__device__ bf16 g_WdL[NH*NT*NV*NV];

__device__ __forceinline__ void split2(float v, bf16& h, bf16& l) {
    h = __float2bfloat16(v);
    l = __float2bfloat16(v - __bfloat162float(h));
}

// bf16x3 GEMM via wmma with 2-stage cp.async pipeline.
// C = A times B (TB=0) or A times B-transpose (TB=1).
// A: [M,K] row-major hi/lo bf16. B: [K,N] row-major (TB=0) or [N,K] row-major (TB=1).
// Output: fp32 C (SPLIT=0) or hi/lo bf16 pair (SPLIT=1).
// Block tile 128 x BNT x 32, 256 threads = 8 warps (4 along M, 2 along N),
// warp tile 32 x (BNT/2): 2 x (BNT/32) wmma 16x16x16 fragments, 3 MMAs per pair.
#define BM 128
#define BK 32

#define SMEM64  69632
#define SMEM128 90112

template<int TB, int SPLIT, int BNT>
__global__ void __launch_bounds__(256) gemmW_k(
    const bf16* __restrict__ AH, const bf16* __restrict__ AL,
    const bf16* __restrict__ BH, const bf16* __restrict__ BL,
    float* __restrict__ CF, bf16* __restrict__ CH, bf16* __restrict__ CL,
    int M, int N, int K, long sA, long sB, long sC)
{
    constexpr int NJ   = BNT / 32;       // B fragments per warp along N
    constexpr int WST  = BNT / 2;        // warp tile width in N
    constexpr int ASTc = 48;             // A smem row stride (elems)
    constexpr int BSTN = BNT + 8;        // B smem row stride, NN layout
    constexpr int BSTT = 40;             // B smem row stride, TB layout
    constexpr int A_BYTES = BM * ASTc * 2;
    constexpr int B_NN = BK * BSTN * 2;
    constexpr int B_TT = BNT * BSTT * 2;
    constexpr int B_BYTES = (B_NN > B_TT) ? B_NN : B_TT;
    constexpr int OFF_AL = A_BYTES;
    constexpr int OFF_BH = 2 * A_BYTES;
    constexpr int OFF_BL = OFF_BH + B_BYTES;
    constexpr int STAGE  = OFF_BL + B_BYTES;
    constexpr int NBR = BNT / 64;        // B load rounds of 256 x 16B

    extern __shared__ char dsm[];

    const bf16* pAH = AH + (long)blockIdx.z * sA;
    const bf16* pAL = AL + (long)blockIdx.z * sA;
    const bf16* pBH = BH + (long)blockIdx.z * sB;
    const bf16* pBL = BL + (long)blockIdx.z * sB;

    int tid = threadIdx.x;
    int row0 = blockIdx.y * BM;
    int col0 = blockIdx.x * BNT;
    int warp = tid >> 5;
    int lane = tid & 31;
    int wm = warp & 3;
    int wn = warp >> 2;

    wmma::fragment<wmma::accumulator, 16, 16, 16, float> acc[2][NJ];
    for (int i = 0; i < 2; i++)
        for (int j = 0; j < NJ; j++)
            wmma::fill_fragment(acc[i][j], 0.0f);

    int nit = K / BK;

    auto load_stage = [&](int it, int st) {
        char* base = dsm + st * STAGE;
        bf16* sAH = (bf16*)(base);
        bf16* sAL = (bf16*)(base + OFF_AL);
        bf16* sBH = (bf16*)(base + OFF_BH);
        bf16* sBL = (bf16*)(base + OFF_BL);
        int k0 = it * BK;
        // A tile 128 x 32
        for (int l = 0; l < 2; l++) {
            int lin = tid + l * 256;
            int r = lin >> 2;
            int c8 = (lin & 3) << 3;
            long g = (long)(row0 + r) * K + k0 + c8;
            __pipeline_memcpy_async(&sAH[r * ASTc + c8], pAH + g, 16);
            __pipeline_memcpy_async(&sAL[r * ASTc + c8], pAL + g, 16);
        }
        if (TB) {
            // tile [BNT rows x BK cols], row stride BSTT
            for (int l = 0; l < NBR; l++) {
                int lin = tid + l * 256;
                int n = lin >> 2;
                int c8 = (lin & 3) << 3;
                long g = (long)(col0 + n) * K + k0 + c8;
                __pipeline_memcpy_async(&sBH[n * BSTT + c8], pBH + g, 16);
                __pipeline_memcpy_async(&sBL[n * BSTT + c8], pBL + g, 16);
            }
        } else {
            // tile [BK rows x BNT cols], row stride BSTN
            constexpr int PR = BNT / 8;
            for (int l = 0; l < NBR; l++) {
                int lin = tid + l * 256;
                int kk = lin / PR;
                int c8 = (lin % PR) * 8;
                long g = (long)(k0 + kk) * N + col0 + c8;
                __pipeline_memcpy_async(&sBH[kk * BSTN + c8], pBH + g, 16);
                __pipeline_memcpy_async(&sBL[kk * BSTN + c8], pBL + g, 16);
            }
        }
    };

    load_stage(0, 0);
    __pipeline_commit();

    for (int it = 0; it < nit; it++) {
        if (it + 1 < nit) {
            load_stage(it + 1, (it + 1) & 1);
            __pipeline_commit();
            __pipeline_wait_prior(1);
        } else {
            __pipeline_wait_prior(0);
        }
        __syncthreads();

        char* base = dsm + (it & 1) * STAGE;
        bf16* sAH = (bf16*)(base);
        bf16* sAL = (bf16*)(base + OFF_AL);
        bf16* sBH = (bf16*)(base + OFF_BH);
        bf16* sBL = (bf16*)(base + OFF_BL);

        for (int kk = 0; kk < BK; kk += 16) {
            wmma::fragment<wmma::matrix_a, 16, 16, 16, bf16, wmma::row_major> aH[2], aL[2];
            for (int i = 0; i < 2; i++) {
                wmma::load_matrix_sync(aH[i], &sAH[(wm * 32 + i * 16) * ASTc + kk], ASTc);
                wmma::load_matrix_sync(aL[i], &sAL[(wm * 32 + i * 16) * ASTc + kk], ASTc);
            }
            for (int j = 0; j < NJ; j++) {
                if (TB) {
                    wmma::fragment<wmma::matrix_b, 16, 16, 16, bf16, wmma::col_major> bH, bL;
                    wmma::load_matrix_sync(bH, &sBH[(wn * WST + j * 16) * BSTT + kk], BSTT);
                    wmma::load_matrix_sync(bL, &sBL[(wn * WST + j * 16) * BSTT + kk], BSTT);
                    for (int i = 0; i < 2; i++) {
                        wmma::mma_sync(acc[i][j], aH[i], bH, acc[i][j]);
                        wmma::mma_sync(acc[i][j], aH[i], bL, acc[i][j]);
                        wmma::mma_sync(acc[i][j], aL[i], bH, acc[i][j]);
                    }
                } else {
                    wmma::fragment<wmma::matrix_b, 16, 16, 16, bf16, wmma::row_major> bH, bL;
                    wmma::load_matrix_sync(bH, &sBH[kk * BSTN + wn * WST + j * 16], BSTN);
                    wmma::load_matrix_sync(bL, &sBL[kk * BSTN + wn * WST + j * 16], BSTN);
                    for (int i = 0; i < 2; i++) {
                        wmma::mma_sync(acc[i][j], aH[i], bH, acc[i][j]);
                        wmma::mma_sync(acc[i][j], aH[i], bL, acc[i][j]);
                        wmma::mma_sync(acc[i][j], aL[i], bH, acc[i][j]);
                    }
                }
            }
        }
        __syncthreads();
    }

    if (SPLIT) {
        // stage accumulators through smem, write hi/lo bf16 pair
        float* st = (float*)dsm + warp * (32 * WST);
        for (int i = 0; i < 2; i++)
            for (int j = 0; j < NJ; j++)
                wmma::store_matrix_sync(st + (i * 16) * WST + j * 16, acc[i][j], WST,
                                        wmma::mem_row_major);
        __syncwarp();
        bf16* pCH = CH + (long)blockIdx.z * sC;
        bf16* pCL = CL + (long)blockIdx.z * sC;
        for (int r = 0; r < 32; r++) {
            for (int l = 0; l < WST / 32; l++) {
                int c = lane + l * 32;
                float v = st[r * WST + c];
                bf16 hi, lo;
                split2(v, hi, lo);
                long off = (long)(row0 + wm * 32 + r) * N + col0 + wn * WST + c;
                pCH[off] = hi;
                pCL[off] = lo;
            }
        }
    } else {
        float* pC = CF + (long)blockIdx.z * sC;
        for (int i = 0; i < 2; i++)
            for (int j = 0; j < NJ; j++) {
                int r = row0 + wm * 32 + i * 16;
                int c = col0 + wn * WST + j * 16;
                wmma::store_matrix_sync(pC + (long)r * N + c, acc[i][j], N,
                                        wmma::mem_row_major);
            }
    }
}

__global__ void __launch_bounds__(256) split_k(const float* __restrict__ s,
                                               bf16* __restrict__ h, bf16* __restrict__ l, long n)
{
    long i = (long)blockIdx.x * 256 + threadIdx.x;
    if (i < n) {
        bf16 hi, lo;
        split2(s[i], hi, lo);
        h[i] = hi;
        l[i] = lo;
    }
}

// softmax over hi/lo bf16 logits in place, scale 1/8
__global__ void __launch_bounds__(256) softmax_k(bf16* __restrict__ scH, bf16* __restrict__ scL)
{
    __shared__ float red[8];
    bf16* pH = scH + (long)blockIdx.x * SQ;
    bf16* pL = scL + (long)blockIdx.x * SQ;
    int tid = threadIdx.x;
    float x[4];
    for (int j = 0; j < 4; j++) {
        int c = tid + j * 256;
        x[j] = (__bfloat162float(pH[c]) + __bfloat162float(pL[c])) * 0.125f;
    }
    float m = fmaxf(fmaxf(x[0], x[1]), fmaxf(x[2], x[3]));
    for (int o = 16; o; o >>= 1) m = fmaxf(m, __shfl_xor_sync(0xffffffffu, m, o));
    if ((tid & 31) == 0) red[tid >> 5] = m;
    __syncthreads();
    for (int w = 0; w < 8; w++) m = fmaxf(m, red[w]);
    float s = 0.f;
    for (int j = 0; j < 4; j++) {
        x[j] = expf(x[j] - m);
        s += x[j];
    }
    for (int o = 16; o; o >>= 1) s += __shfl_xor_sync(0xffffffffu, s, o);
    __syncthreads();
    if ((tid & 31) == 0) red[tid >> 5] = s;
    __syncthreads();
    s = 0.f;
    for (int w = 0; w < 8; w++) s += red[w];
    float inv = 1.f / s;
    for (int j = 0; j < 4; j++) {
        int c = tid + j * 256;
        bf16 hi, lo;
        split2(x[j] * inv, hi, lo);
        pH[c] = hi;
        pL[c] = lo;
    }
}

__global__ void __launch_bounds__(256) resid_reduce_k(
    float* __restrict__ net, const float* __restrict__ add,
    float* __restrict__ stats, int relu)
{
    int h = blockIdx.y;
    int chunk = blockIdx.x;
    int c = threadIdx.x;
    long base = ((long)h * RR + (long)chunk * 64) * NV + c;
    float s = 0.f;
    float s2 = 0.f;
    for (int r = 0; r < 64; r++) {
        long idx = base + (long)r * NV;
        float a = add[idx];
        if (relu) a = fmaxf(a, 0.f);
        float val = net[idx] + a;
        net[idx] = val;
        s += val;
        s2 += val * val;
    }
    atomicAdd(&stats[h * NV + c], s);
    atomicAdd(&stats[NH * NV + h * NV + c], s2);
}

__global__ void __launch_bounds__(256) bn_apply_k(
    float* __restrict__ net, bf16* __restrict__ netH, bf16* __restrict__ netL,
    const float* __restrict__ stats,
    const float* __restrict__ gamma, const float* __restrict__ beta, int t)
{
    long idx = (long)blockIdx.x * 256 + threadIdx.x;
    int c = (int)(idx & (NV - 1));
    int h = (int)(idx >> 20);
    float mean = stats[h * NV + c] * (1.f / RR);
    float ex2  = stats[NH * NV + h * NV + c] * (1.f / RR);
    float var  = ex2 - mean * mean;
    float g = gamma[(h * NT + t) * NV + c];
    float b = beta [(h * NT + t) * NV + c];
    float val = (net[idx] - mean) * rsqrtf(var + EPSBN) * g + b;
    net[idx] = val;
    bf16 hi, lo;
    split2(val, hi, lo);
    netH[idx] = hi;
    netL[idx] = lo;
}

__global__ void __launch_bounds__(256) bcast_k(
    float* __restrict__ net, bf16* __restrict__ netH, bf16* __restrict__ netL,
    const float* __restrict__ net0)
{
    long idx = (long)blockIdx.x * 256 + threadIdx.x;
    float v = net0[idx];
    bf16 hi, lo;
    split2(v, hi, lo);
    for (int h = 0; h < NH; h++) {
        long o = (long)h * RR * NV + idx;
        net[o] = v;
        netH[o] = hi;
        netL[o] = lo;
    }
}

__global__ void __launch_bounds__(256) final_k(float* __restrict__ out,
                                               const float* __restrict__ net)
{
    long idx = (long)blockIdx.x * 256 + threadIdx.x;
    int c = (int)(idx & (NV - 1));
    int h = (int)((idx >> 8) & (NH - 1));
    long bs = idx >> 11;
    out[idx] = net[((long)h * RR + bs) * NV + c];
}

extern "C" void kernel_launch(void* const* d_in, const int* in_sizes, int n_in,
                              void* d_out, int out_size)
{
    (void)in_sizes;
    (void)n_in;
    (void)out_size;
    const float* x    = (const float*)d_in[0];
    const float* W_in = (const float*)d_in[1];
    const float* Wq   = (const float*)d_in[2];
    const float* Wk   = (const float*)d_in[3];
    const float* Wv   = (const float*)d_in[4];
    const float* Wd   = (const float*)d_in[5];
    const float* g1   = (const float*)d_in[6];
    const float* b1   = (const float*)d_in[7];
    const float* g2   = (const float*)d_in[8];
    const float* b2   = (const float*)d_in[9];
    float* out = (float*)d_out;

    float* net;
    float* net0;
    float* tmp;
    float* stats;
    bf16* netH;
    bf16* netL;
    bf16* qH;
    bf16* qL;
    bf16* kH;
    bf16* kL;
    bf16* vH;
    bf16* vL;
    bf16* scH;
    bf16* scL;
    bf16* xH;
    bf16* xL;
    bf16* WinH;
    bf16* WinL;
    bf16* WqH;
    bf16* WqL;
    bf16* WkH;
    bf16* WkL;
    bf16* WvH;
    bf16* WvL;
    bf16* WdH;
    bf16* WdL;
    cudaGetSymbolAddress((void**)&net,  g_net);
    cudaGetSymbolAddress((void**)&net0, g_net0);
    cudaGetSymbolAddress((void**)&tmp,  g_tmp);
    cudaGetSymbolAddress((void**)&stats, g_stats);
    cudaGetSymbolAddress((void**)&netH, g_netH);
    cudaGetSymbolAddress((void**)&netL, g_netL);
    cudaGetSymbolAddress((void**)&qH,   g_qH);
    cudaGetSymbolAddress((void**)&qL,   g_qL);
    cudaGetSymbolAddress((void**)&kH,   g_kH);
    cudaGetSymbolAddress((void**)&kL,   g_kL);
    cudaGetSymbolAddress((void**)&vH,   g_vH);
    cudaGetSymbolAddress((void**)&vL,   g_vL);
    cudaGetSymbolAddress((void**)&scH,  g_scH);
    cudaGetSymbolAddress((void**)&scL,  g_scL);
    cudaGetSymbolAddress((void**)&xH,   g_xH);
    cudaGetSymbolAddress((void**)&xL,   g_xL);
    cudaGetSymbolAddress((void**)&WinH, g_WinH);
    cudaGetSymbolAddress((void**)&WinL, g_WinL);
    cudaGetSymbolAddress((void**)&WqH,  g_WqH);
    cudaGetSymbolAddress((void**)&WqL,  g_WqL);
    cudaGetSymbolAddress((void**)&WkH,  g_WkH);
    cudaGetSymbolAddress((void**)&WkL,  g_WkL);
    cudaGetSymbolAddress((void**)&WvH,  g_WvH);
    cudaGetSymbolAddress((void**)&WvL,  g_WvL);
    cudaGetSymbolAddress((void**)&WdH,  g_WdH);
    cudaGetSymbolAddress((void**)&WdL,  g_WdL);

    cudaFuncSetAttribute(gemmW_k<0, 0, 128>, cudaFuncAttributeMaxDynamicSharedMemorySize, SMEM128);
    cudaFuncSetAttribute(gemmW_k<0, 1, 128>, cudaFuncAttributeMaxDynamicSharedMemorySize, SMEM128);
    cudaFuncSetAttribute(gemmW_k<1, 1, 128>, cudaFuncAttributeMaxDynamicSharedMemorySize, SMEM128);
    cudaFuncSetAttribute(gemmW_k<0, 1, 64>,  cudaFuncAttributeMaxDynamicSharedMemorySize, SMEM64);

    const long RV = (long)RR * NV;
    const long RK = (long)RR * NKD;
    const long SS = (long)SQ * SQ;
    const long WQK = (long)NV * NKD;
    const long WVV = (long)NV * NV;

    split_k<<<(int)(RV / 256), 256>>>(x, xH, xL, RV);
    split_k<<<(int)(WVV / 256), 256>>>(W_in, WinH, WinL, WVV);
    split_k<<<(int)((NH * NT * WQK) / 256), 256>>>(Wq, WqH, WqL, NH * NT * WQK);
    split_k<<<(int)((NH * NT * WQK) / 256), 256>>>(Wk, WkH, WkL, NH * NT * WQK);
    split_k<<<(int)((NH * NT * WVV) / 256), 256>>>(Wv, WvH, WvL, NH * NT * WVV);
    split_k<<<(int)((NH * NT * WVV) / 256), 256>>>(Wd, WdH, WdL, NH * NT * WVV);

    gemmW_k<0, 0, 128><<<dim3(2, 32, 1), 256, SMEM128>>>(
        xH, xL, WinH, WinL, net0, (bf16*)0, (bf16*)0, RR, NV, 256, 0, 0, 0);
    bcast_k<<<(int)(RV / 256), 256>>>(net, netH, netL, net0);

    for (int t = 0; t < NT; t++) {
        gemmW_k<0, 1, 64><<<dim3(1, 32, NH), 256, SMEM64>>>(
            netH, netL, WqH + (long)t * WQK, WqL + (long)t * WQK,
            (float*)0, qH, qL, RR, NKD, NV, RV, (long)NT * WQK, RK);
        gemmW_k<0, 1, 64><<<dim3(1, 32, NH), 256, SMEM64>>>(
            netH, netL, WkH + (long)t * WQK, WkL + (long)t * WQK,
            (float*)0, kH, kL, RR, NKD, NV, RV, (long)NT * WQK, RK);
        gemmW_k<0, 1, 128><<<dim3(2, 32, NH), 256, SMEM128>>>(
            netH, netL, WvH + (long)t * WVV, WvL + (long)t * WVV,
            (float*)0, vH, vL, RR, NV, NV, RV, (long)NT * WVV, RV);

        gemmW_k<1, 1, 128><<<dim3(8, 8, NZ), 256, SMEM128>>>(
            qH, qL, kH, kL, (float*)0, scH, scL,
            SQ, SQ, NKD, (long)SQ * NKD, (long)SQ * NKD, SS);
        softmax_k<<<NZ * SQ, 256>>>(scH, scL);
        gemmW_k<0, 0, 128><<<dim3(2, 8, NZ), 256, SMEM128>>>(
            scH, scL, vH, vL, tmp, (bf16*)0, (bf16*)0,
            SQ, NV, SQ, SS, (long)SQ * NV, (long)SQ * NV);

        cudaMemsetAsync(stats, 0, sizeof(float) * 2 * NH * NV);
        resid_reduce_k<<<dim3(RR / 64, NH), 256>>>(net, tmp, stats, 0);
        bn_apply_k<<<(int)((NH * RV) / 256), 256>>>(net, netH, netL, stats, g1, b1, t);

        gemmW_k<0, 0, 128><<<dim3(2, 32, NH), 256, SMEM128>>>(
            netH, netL, WdH + (long)t * WVV, WdL + (long)t * WVV,
            tmp, (bf16*)0, (bf16*)0, RR, NV, NV, RV, (long)NT * WVV, RV);

        cudaMemsetAsync(stats, 0, sizeof(float) * 2 * NH * NV);
        resid_reduce_k<<<dim3(RR / 64, NH), 256>>>(net, tmp, stats, 1);
        bn_apply_k<<<(int)((NH * RV) / 256), 256>>>(net, netH, netL, stats, g2, b2, t);
    }

    final_k<<<(int)(((long)NB * SQ * NH * NV) / 256), 256>>>(out, net);
}

// round 13
// speedup vs baseline: 1.6565x; 1.0263x over previous
#include <cuda_runtime.h>
#include <cuda_bf16.h>
#include <cuda_pipeline.h>
#include <mma.h>
#include <cstdint>

using namespace nvcuda;

#define NH   8
#define NT   4
#define NB   4
#define SQ   1024
#define NV   256
#define NKD  64
#define RR   4096
#define NZ   32
#define EPSBN 1e-3f

typedef __nv_bfloat16 bf16;

__device__ float g_net [(long)NH*RR*NV];
__device__ float g_net0[(long)RR*NV];
__device__ float g_tmp [(long)NH*RR*NV];
__device__ float g_stats[2*NH*NV];

__device__ bf16 g_netH[(long)NH*RR*NV];
__device__ bf16 g_netL[(long)NH*RR*NV];
__device__ bf16 g_qH[(long)NH*RR*NKD];
__device__ bf16 g_qL[(long)NH*RR*NKD];
__device__ bf16 g_kH[(long)NH*RR*NKD];
__device__ bf16 g_kL[(long)NH*RR*NKD];
__device__ bf16 g_vH[(long)NH*RR*NV];
__device__ bf16 g_vL[(long)NH*RR*NV];
__device__ bf16 g_xH[(long)RR*256];
__device__ bf16 g_xL[(long)RR*256];
__device__ bf16 g_WinH[256*NV];
__device__ bf16 g_WinL[256*NV];
__device__ bf16 g_WqH[NH*NT*NV*NKD];
__device__ bf16 g_WqL[NH*NT*NV*NKD];
__device__ bf16 g_WkH[NH*NT*NV*NKD];
__device__ bf16 g_WkL[NH*NT*NV*NKD];
__device__ bf16 g_WvH[NH*NT*NV*NV];
__device__ bf16 g_WvL[NH*NT*NV*NV];
__device__ bf16 g_WdH[NH*NT*NV*NV];
__device__ bf16 g_WdL[NH*NT*NV*NV];

__device__ __forceinline__ void split2(float v, bf16& h, bf16& l) {
    h = __float2bfloat16(v);
    l = __float2bfloat16(v - __bfloat162float(h));
}

// ---------------- generic bf16x3 GEMM (unchanged from R12) ----------------
#define BM 128
#define BK 32

#define SMEM64  69632
#define SMEM128 90112

template<int TB, int SPLIT, int BNT>
__global__ void __launch_bounds__(256) gemmW_k(
    const bf16* __restrict__ AH, const bf16* __restrict__ AL,
    const bf16* __restrict__ BH, const bf16* __restrict__ BL,
    float* __restrict__ CF, bf16* __restrict__ CH, bf16* __restrict__ CL,
    int M, int N, int K, long sA, long sB, long sC)
{
    constexpr int NJ   = BNT / 32;
    constexpr int WST  = BNT / 2;
    constexpr int ASTc = 48;
    constexpr int BSTN = BNT + 8;
    constexpr int BSTT = 40;
    constexpr int A_BYTES = BM * ASTc * 2;
    constexpr int B_NN = BK * BSTN * 2;
    constexpr int B_TT = BNT * BSTT * 2;
    constexpr int B_BYTES = (B_NN > B_TT) ? B_NN : B_TT;
    constexpr int OFF_AL = A_BYTES;
    constexpr int OFF_BH = 2 * A_BYTES;
    constexpr int OFF_BL = OFF_BH + B_BYTES;
    constexpr int STAGE  = OFF_BL + B_BYTES;
    constexpr int NBR = BNT / 64;

    extern __shared__ char dsm[];

    const bf16* pAH = AH + (long)blockIdx.z * sA;
    const bf16* pAL = AL + (long)blockIdx.z * sA;
    const bf16* pBH = BH + (long)blockIdx.z * sB;
    const bf16* pBL = BL + (long)blockIdx.z * sB;

    int tid = threadIdx.x;
    int row0 = blockIdx.y * BM;
    int col0 = blockIdx.x * BNT;
    int warp = tid >> 5;
    int lane = tid & 31;
    int wm = warp & 3;
    int wn = warp >> 2;

    wmma::fragment<wmma::accumulator, 16, 16, 16, float> acc[2][NJ];
    for (int i = 0; i < 2; i++)
        for (int j = 0; j < NJ; j++)
            wmma::fill_fragment(acc[i][j], 0.0f);

    int nit = K / BK;

    auto load_stage = [&](int it, int st) {
        char* base = dsm + st * STAGE;
        bf16* sAH = (bf16*)(base);
        bf16* sAL = (bf16*)(base + OFF_AL);
        bf16* sBH = (bf16*)(base + OFF_BH);
        bf16* sBL = (bf16*)(base + OFF_BL);
        int k0 = it * BK;
        for (int l = 0; l < 2; l++) {
            int lin = tid + l * 256;
            int r = lin >> 2;
            int c8 = (lin & 3) << 3;
            long g = (long)(row0 + r) * K + k0 + c8;
            __pipeline_memcpy_async(&sAH[r * ASTc + c8], pAH + g, 16);
            __pipeline_memcpy_async(&sAL[r * ASTc + c8], pAL + g, 16);
        }
        if (TB) {
            for (int l = 0; l < NBR; l++) {
                int lin = tid + l * 256;
                int n = lin >> 2;
                int c8 = (lin & 3) << 3;
                long g = (long)(col0 + n) * K + k0 + c8;
                __pipeline_memcpy_async(&sBH[n * BSTT + c8], pBH + g, 16);
                __pipeline_memcpy_async(&sBL[n * BSTT + c8], pBL + g, 16);
            }
        } else {
            constexpr int PR = BNT / 8;
            for (int l = 0; l < NBR; l++) {
                int lin = tid + l * 256;
                int kk = lin / PR;
                int c8 = (lin % PR) * 8;
                long g = (long)(k0 + kk) * N + col0 + c8;
                __pipeline_memcpy_async(&sBH[kk * BSTN + c8], pBH + g, 16);
                __pipeline_memcpy_async(&sBL[kk * BSTN + c8], pBL + g, 16);
            }
        }
    };

    load_stage(0, 0);
    __pipeline_commit();

    for (int it = 0; it < nit; it++) {
        if (it + 1 < nit) {
            load_stage(it + 1, (it + 1) & 1);
            __pipeline_commit();
            __pipeline_wait_prior(1);
        } else {
            __pipeline_wait_prior(0);
        }
        __syncthreads();

        char* base = dsm + (it & 1) * STAGE;
        bf16* sAH = (bf16*)(base);
        bf16* sAL = (bf16*)(base + OFF_AL);
        bf16* sBH = (bf16*)(base + OFF_BH);
        bf16* sBL = (bf16*)(base + OFF_BL);

        for (int kk = 0; kk < BK; kk += 16) {
            wmma::fragment<wmma::matrix_a, 16, 16, 16, bf16, wmma::row_major> aH[2], aL[2];
            for (int i = 0; i < 2; i++) {
                wmma::load_matrix_sync(aH[i], &sAH[(wm * 32 + i * 16) * ASTc + kk], ASTc);
                wmma::load_matrix_sync(aL[i], &sAL[(wm * 32 + i * 16) * ASTc + kk], ASTc);
            }
            for (int j = 0; j < NJ; j++) {
                if (TB) {
                    wmma::fragment<wmma::matrix_b, 16, 16, 16, bf16, wmma::col_major> bH, bL;
                    wmma::load_matrix_sync(bH, &sBH[(wn * WST + j * 16) * BSTT + kk], BSTT);
                    wmma::load_matrix_sync(bL, &sBL[(wn * WST + j * 16) * BSTT + kk], BSTT);
                    for (int i = 0; i < 2; i++) {
                        wmma::mma_sync(acc[i][j], aH[i], bH, acc[i][j]);
                        wmma::mma_sync(acc[i][j], aH[i], bL, acc[i][j]);
                        wmma::mma_sync(acc[i][j], aL[i], bH, acc[i][j]);
                    }
                } else {
                    wmma::fragment<wmma::matrix_b, 16, 16, 16, bf16, wmma::row_major> bH, bL;
                    wmma::load_matrix_sync(bH, &sBH[kk * BSTN + wn * WST + j * 16], BSTN);
                    wmma::load_matrix_sync(bL, &sBL[kk * BSTN + wn * WST + j * 16], BSTN);
                    for (int i = 0; i < 2; i++) {
                        wmma::mma_sync(acc[i][j], aH[i], bH, acc[i][j]);
                        wmma::mma_sync(acc[i][j], aH[i], bL, acc[i][j]);
                        wmma::mma_sync(acc[i][j], aL[i], bH, acc[i][j]);
                    }
                }
            }
        }
        __syncthreads();
    }

    if (SPLIT) {
        float* st = (float*)dsm + warp * (32 * WST);
        for (int i = 0; i < 2; i++)
            for (int j = 0; j < NJ; j++)
                wmma::store_matrix_sync(st + (i * 16) * WST + j * 16, acc[i][j], WST,
                                        wmma::mem_row_major);
        __syncwarp();
        bf16* pCH = CH + (long)blockIdx.z * sC;
        bf16* pCL = CL + (long)blockIdx.z * sC;
        for (int r = 0; r < 32; r++) {
            for (int l = 0; l < WST / 32; l++) {
                int c = lane + l * 32;
                float v = st[r * WST + c];
                bf16 hi, lo;
                split2(v, hi, lo);
                long off = (long)(row0 + wm * 32 + r) * N + col0 + wn * WST + c;
                pCH[off] = hi;
                pCL[off] = lo;
            }
        }
    } else {
        float* pC = CF + (long)blockIdx.z * sC;
        for (int i = 0; i < 2; i++)
            for (int j = 0; j < NJ; j++) {
                int r = row0 + wm * 32 + i * 16;
                int c = col0 + wn * WST + j * 16;
                wmma::store_matrix_sync(pC + (long)r * N + c, acc[i][j], N,
                                        wmma::mem_row_major);
            }
    }
}

// ---------------- fused attention: O = softmax(Q K^T / 8) V ----------------
// One CTA per (z, 128-row Q stripe). KV tiles of 32 rows, double-buffered
// cp.async. No-max softmax (bounded logits): P_unnorm = exp(s/8), row sums
// accumulated in smem, final 1/l scaling in the epilogue.
// Smem layout (bytes):
#define FOQH 0
#define FOQL 18432
#define FOKH 36864
#define FOKL 46080
#define FOVH 55296
#define FOVL 89088
#define FOS  122880
#define FOPH 141312
#define FOPL 151552
#define FOML 161792
#define FSMEM 162304

__global__ void __launch_bounds__(256, 1) fattn_k(
    const bf16* __restrict__ qH_, const bf16* __restrict__ qL_,
    const bf16* __restrict__ kH_, const bf16* __restrict__ kL_,
    const bf16* __restrict__ vH_, const bf16* __restrict__ vL_,
    float* __restrict__ tmp_)
{
    extern __shared__ char dsm[];
    int tid = threadIdx.x;
    int z = blockIdx.z;
    int row0 = blockIdx.x * 128;
    int warp = tid >> 5;
    int lane = tid & 31;
    int wm = warp & 3;
    int wn = warp >> 2;

    const bf16* pQH = qH_ + (long)z * SQ * NKD + (long)row0 * NKD;
    const bf16* pQL = qL_ + (long)z * SQ * NKD + (long)row0 * NKD;
    const bf16* pKH = kH_ + (long)z * SQ * NKD;
    const bf16* pKL = kL_ + (long)z * SQ * NKD;
    const bf16* pVH = vH_ + (long)z * SQ * NV;
    const bf16* pVL = vL_ + (long)z * SQ * NV;

    bf16* Qh = (bf16*)(dsm + FOQH);
    bf16* Ql = (bf16*)(dsm + FOQL);
    float* Ssm = (float*)(dsm + FOS);
    bf16* Ph = (bf16*)(dsm + FOPH);
    bf16* Pl = (bf16*)(dsm + FOPL);
    float* lsm = (float*)(dsm + FOML);

    // load Q stripe 128x64 hi/lo, stride 72
    for (int l = 0; l < 4; l++) {
        int idx = tid + l * 256;
        int r = idx >> 3;
        int c8 = (idx & 7) << 3;
        __pipeline_memcpy_async(&Qh[r * 72 + c8], pQH + (long)r * NKD + c8, 16);
        __pipeline_memcpy_async(&Ql[r * 72 + c8], pQL + (long)r * NKD + c8, 16);
    }
    if (tid < 128) lsm[tid] = 0.0f;

    auto load_kv = [&](int it, int st) {
        bf16* kh = (bf16*)(dsm + FOKH + st * 4608);
        bf16* kl = (bf16*)(dsm + FOKL + st * 4608);
        bf16* vh = (bf16*)(dsm + FOVH + st * 16896);
        bf16* vl = (bf16*)(dsm + FOVL + st * 16896);
        int kv0 = it * 32;
        {
            int r = tid >> 3;
            int c8 = (tid & 7) << 3;
            __pipeline_memcpy_async(&kh[r * 72 + c8], pKH + (long)(kv0 + r) * NKD + c8, 16);
            __pipeline_memcpy_async(&kl[r * 72 + c8], pKL + (long)(kv0 + r) * NKD + c8, 16);
        }
        for (int l2 = 0; l2 < 4; l2++) {
            int idx = tid + l2 * 256;
            int r = idx >> 5;
            int c8 = (idx & 31) << 3;
            __pipeline_memcpy_async(&vh[r * 264 + c8], pVH + (long)(kv0 + r) * NV + c8, 16);
            __pipeline_memcpy_async(&vl[r * 264 + c8], pVL + (long)(kv0 + r) * NV + c8, 16);
        }
    };

    load_kv(0, 0);
    __pipeline_commit();

    wmma::fragment<wmma::accumulator, 16, 16, 16, float> oa[2][8];
    for (int i = 0; i < 2; i++)
        for (int j = 0; j < 8; j++)
            wmma::fill_fragment(oa[i][j], 0.0f);

    for (int it = 0; it < 32; it++) {
        __pipeline_wait_prior(0);
        __syncthreads();
        if (it + 1 < 32) {
            load_kv(it + 1, (it + 1) & 1);
            __pipeline_commit();
        }
        int st = it & 1;
        bf16* kh = (bf16*)(dsm + FOKH + st * 4608);
        bf16* kl = (bf16*)(dsm + FOKL + st * 4608);
        bf16* vh = (bf16*)(dsm + FOVH + st * 16896);
        bf16* vl = (bf16*)(dsm + FOVL + st * 16896);

        // S = Q @ K^T  (128 x 32), warp tile 32x16
        wmma::fragment<wmma::accumulator, 16, 16, 16, float> sa[2];
        wmma::fill_fragment(sa[0], 0.0f);
        wmma::fill_fragment(sa[1], 0.0f);
        for (int kk = 0; kk < 64; kk += 16) {
            wmma::fragment<wmma::matrix_a, 16, 16, 16, bf16, wmma::row_major> aH[2], aL[2];
            for (int i = 0; i < 2; i++) {
                wmma::load_matrix_sync(aH[i], &Qh[(wm * 32 + i * 16) * 72 + kk], 72);
                wmma::load_matrix_sync(aL[i], &Ql[(wm * 32 + i * 16) * 72 + kk], 72);
            }
            wmma::fragment<wmma::matrix_b, 16, 16, 16, bf16, wmma::col_major> bH, bL;
            wmma::load_matrix_sync(bH, &kh[(wn * 16) * 72 + kk], 72);
            wmma::load_matrix_sync(bL, &kl[(wn * 16) * 72 + kk], 72);
            for (int i = 0; i < 2; i++) {
                wmma::mma_sync(sa[i], aH[i], bH, sa[i]);
                wmma::mma_sync(sa[i], aH[i], bL, sa[i]);
                wmma::mma_sync(sa[i], aL[i], bH, sa[i]);
            }
        }
        for (int i = 0; i < 2; i++)
            wmma::store_matrix_sync(&Ssm[(wm * 32 + i * 16) * 36 + wn * 16], sa[i], 36,
                                    wmma::mem_row_major);
        __syncthreads();

        // P_unnorm = exp(S/8), accumulate row sums, split to bf16 hi/lo
        {
            int r = tid >> 1;
            int h2 = tid & 1;
            float lsum = 0.0f;
            for (int c = 0; c < 16; c++) {
                float e = expf(Ssm[r * 36 + h2 * 16 + c] * 0.125f);
                lsum += e;
                bf16 hi, lo;
                split2(e, hi, lo);
                Ph[r * 40 + h2 * 16 + c] = hi;
                Pl[r * 40 + h2 * 16 + c] = lo;
            }
            lsum += __shfl_xor_sync(0xffffffffu, lsum, 1);
            if (h2 == 0) lsm[r] += lsum;
        }
        __syncthreads();

        // O += P_unnorm @ V  (128 x 256), warp tile 32x128
        for (int kk = 0; kk < 32; kk += 16) {
            wmma::fragment<wmma::matrix_a, 16, 16, 16, bf16, wmma::row_major> aH[2], aL[2];
            for (int i = 0; i < 2; i++) {
                wmma::load_matrix_sync(aH[i], &Ph[(wm * 32 + i * 16) * 40 + kk], 40);
                wmma::load_matrix_sync(aL[i], &Pl[(wm * 32 + i * 16) * 40 + kk], 40);
            }
            for (int j = 0; j < 8; j++) {
                wmma::fragment<wmma::matrix_b, 16, 16, 16, bf16, wmma::row_major> bH, bL;
                wmma::load_matrix_sync(bH, &vh[kk * 264 + wn * 128 + j * 16], 264);
                wmma::load_matrix_sync(bL, &vl[kk * 264 + wn * 128 + j * 16], 264);
                for (int i = 0; i < 2; i++) {
                    wmma::mma_sync(oa[i][j], aH[i], bH, oa[i][j]);
                    wmma::mma_sync(oa[i][j], aH[i], bL, oa[i][j]);
                    wmma::mma_sync(oa[i][j], aL[i], bH, oa[i][j]);
                }
            }
        }
    }

    __syncthreads();
    if (tid < 128) lsm[tid] = 1.0f / lsm[tid];
    __syncthreads();

    // epilogue: stage O through smem (layout known), scale by 1/l, store fp32
    float* stg = (float*)(dsm) + warp * 4096;
    for (int i = 0; i < 2; i++)
        for (int j = 0; j < 8; j++)
            wmma::store_matrix_sync(stg + (i * 16) * 128 + j * 16, oa[i][j], 128,
                                    wmma::mem_row_major);
    __syncwarp();
    float* pO = tmp_ + (long)z * SQ * NV + (long)(row0 + wm * 32) * NV + wn * 128;
    for (int r = 0; r < 32; r++) {
        float sc = lsm[wm * 32 + r];
        for (int l3 = 0; l3 < 4; l3++) {
            int c = lane + l3 * 32;
            pO[(long)r * NV + c] = stg[r * 128 + c] * sc;
        }
    }
}

__global__ void __launch_bounds__(256) split_k(const float* __restrict__ s,
                                               bf16* __restrict__ h, bf16* __restrict__ l, long n)
{
    long i = (long)blockIdx.x * 256 + threadIdx.x;
    if (i < n) {
        bf16 hi, lo;
        split2(s[i], hi, lo);
        h[i] = hi;
        l[i] = lo;
    }
}

__global__ void __launch_bounds__(256) resid_reduce_k(
    float* __restrict__ net, const float* __restrict__ add,
    float* __restrict__ stats, int relu)
{
    int h = blockIdx.y;
    int chunk = blockIdx.x;
    int c = threadIdx.x;
    long base = ((long)h * RR + (long)chunk * 64) * NV + c;
    float s = 0.f;
    float s2 = 0.f;
    for (int r = 0; r < 64; r++) {
        long idx = base + (long)r * NV;
        float a = add[idx];
        if (relu) a = fmaxf(a, 0.f);
        float val = net[idx] + a;
        net[idx] = val;
        s += val;
        s2 += val * val;
    }
    atomicAdd(&stats[h * NV + c], s);
    atomicAdd(&stats[NH * NV + h * NV + c], s2);
}

__global__ void __launch_bounds__(256) bn_apply_k(
    float* __restrict__ net, bf16* __restrict__ netH, bf16* __restrict__ netL,
    const float* __restrict__ stats,
    const float* __restrict__ gamma, const float* __restrict__ beta, int t)
{
    long idx = (long)blockIdx.x * 256 + threadIdx.x;
    int c = (int)(idx & (NV - 1));
    int h = (int)(idx >> 20);
    float mean = stats[h * NV + c] * (1.f / RR);
    float ex2  = stats[NH * NV + h * NV + c] * (1.f / RR);
    float var  = ex2 - mean * mean;
    float g = gamma[(h * NT + t) * NV + c];
    float b = beta [(h * NT + t) * NV + c];
    float val = (net[idx] - mean) * rsqrtf(var + EPSBN) * g + b;
    net[idx] = val;
    bf16 hi, lo;
    split2(val, hi, lo);
    netH[idx] = hi;
    netL[idx] = lo;
}

__global__ void __launch_bounds__(256) bcast_k(
    float* __restrict__ net, bf16* __restrict__ netH, bf16* __restrict__ netL,
    const float* __restrict__ net0)
{
    long idx = (long)blockIdx.x * 256 + threadIdx.x;
    float v = net0[idx];
    bf16 hi, lo;
    split2(v, hi, lo);
    for (int h = 0; h < NH; h++) {
        long o = (long)h * RR * NV + idx;
        net[o] = v;
        netH[o] = hi;
        netL[o] = lo;
    }
}

__global__ void __launch_bounds__(256) final_k(float* __restrict__ out,
                                               const float* __restrict__ net)
{
    long idx = (long)blockIdx.x * 256 + threadIdx.x;
    int c = (int)(idx & (NV - 1));
    int h = (int)((idx >> 8) & (NH - 1));
    long bs = idx >> 11;
    out[idx] = net[((long)h * RR + bs) * NV + c];
}

extern "C" void kernel_launch(void* const* d_in, const int* in_sizes, int n_in,
                              void* d_out, int out_size)
{
    (void)in_sizes;
    (void)n_in;
    (void)out_size;
    const float* x    = (const float*)d_in[0];
    const float* W_in = (const float*)d_in[1];
    const float* Wq   = (const float*)d_in[2];
    const float* Wk   = (const float*)d_in[3];
    const float* Wv   = (const float*)d_in[4];
    const float* Wd   = (const float*)d_in[5];
    const float* g1   = (const float*)d_in[6];
    const float* b1   = (const float*)d_in[7];
    const float* g2   = (const float*)d_in[8];
    const float* b2   = (const float*)d_in[9];
    float* out = (float*)d_out;

    float* net;
    float* net0;
    float* tmp;
    float* stats;
    bf16* netH;
    bf16* netL;
    bf16* qH;
    bf16* qL;
    bf16* kH;
    bf16* kL;
    bf16* vH;
    bf16* vL;
    bf16* xH;
    bf16* xL;
    bf16* WinH;
    bf16* WinL;
    bf16* WqH;
    bf16* WqL;
    bf16* WkH;
    bf16* WkL;
    bf16* WvH;
    bf16* WvL;
    bf16* WdH;
    bf16* WdL;
    cudaGetSymbolAddress((void**)&net,  g_net);
    cudaGetSymbolAddress((void**)&net0, g_net0);
    cudaGetSymbolAddress((void**)&tmp,  g_tmp);
    cudaGetSymbolAddress((void**)&stats, g_stats);
    cudaGetSymbolAddress((void**)&netH, g_netH);
    cudaGetSymbolAddress((void**)&netL, g_netL);
    cudaGetSymbolAddress((void**)&qH,   g_qH);
    cudaGetSymbolAddress((void**)&qL,   g_qL);
    cudaGetSymbolAddress((void**)&kH,   g_kH);
    cudaGetSymbolAddress((void**)&kL,   g_kL);
    cudaGetSymbolAddress((void**)&vH,   g_vH);
    cudaGetSymbolAddress((void**)&vL,   g_vL);
    cudaGetSymbolAddress((void**)&xH,   g_xH);
    cudaGetSymbolAddress((void**)&xL,   g_xL);
    cudaGetSymbolAddress((void**)&WinH, g_WinH);
    cudaGetSymbolAddress((void**)&WinL, g_WinL);
    cudaGetSymbolAddress((void**)&WqH,  g_WqH);
    cudaGetSymbolAddress((void**)&WqL,  g_WqL);
    cudaGetSymbolAddress((void**)&WkH,  g_WkH);
    cudaGetSymbolAddress((void**)&WkL,  g_WkL);
    cudaGetSymbolAddress((void**)&WvH,  g_WvH);
    cudaGetSymbolAddress((void**)&WvL,  g_WvL);
    cudaGetSymbolAddress((void**)&WdH,  g_WdH);
    cudaGetSymbolAddress((void**)&WdL,  g_WdL);

    cudaFuncSetAttribute(gemmW_k<0, 0, 128>, cudaFuncAttributeMaxDynamicSharedMemorySize, SMEM128);
    cudaFuncSetAttribute(gemmW_k<0, 1, 128>, cudaFuncAttributeMaxDynamicSharedMemorySize, SMEM128);
    cudaFuncSetAttribute(gemmW_k<0, 1, 64>,  cudaFuncAttributeMaxDynamicSharedMemorySize, SMEM64);
    cudaFuncSetAttribute(fattn_k, cudaFuncAttributeMaxDynamicSharedMemorySize, FSMEM);

    const long RV = (long)RR * NV;
    const long RK = (long)RR * NKD;
    const long WQK = (long)NV * NKD;
    const long WVV = (long)NV * NV;

    split_k<<<(int)(RV / 256), 256>>>(x, xH, xL, RV);
    split_k<<<(int)(WVV / 256), 256>>>(W_in, WinH, WinL, WVV);
    split_k<<<(int)((NH * NT * WQK) / 256), 256>>>(Wq, WqH, WqL, NH * NT * WQK);
    split_k<<<(int)((NH * NT * WQK) / 256), 256>>>(Wk, WkH, WkL, NH * NT * WQK);
    split_k<<<(int)((NH * NT * WVV) / 256), 256>>>(Wv, WvH, WvL, NH * NT * WVV);
    split_k<<<(int)((NH * NT * WVV) / 256), 256>>>(Wd, WdH, WdL, NH * NT * WVV);

    gemmW_k<0, 0, 128><<<dim3(2, 32, 1), 256, SMEM128>>>(
        xH, xL, WinH, WinL, net0, (bf16*)0, (bf16*)0, RR, NV, 256, 0, 0, 0);
    bcast_k<<<(int)(RV / 256), 256>>>(net, netH, netL, net0);

    for (int t = 0; t < NT; t++) {
        gemmW_k<0, 1, 64><<<dim3(1, 32, NH), 256, SMEM64>>>(
            netH, netL, WqH + (long)t * WQK, WqL + (long)t * WQK,
            (float*)0, qH, qL, RR, NKD, NV, RV, (long)NT * WQK, RK);
        gemmW_k<0, 1, 64><<<dim3(1, 32, NH), 256, SMEM64>>>(
            netH, netL, WkH + (long)t * WQK, WkL + (long)t * WQK,
            (float*)0, kH, kL, RR, NKD, NV, RV, (long)NT * WQK, RK);
        gemmW_k<0, 1, 128><<<dim3(2, 32, NH), 256, SMEM128>>>(
            netH, netL, WvH + (long)t * WVV, WvL + (long)t * WVV,
            (float*)0, vH, vL, RR, NV, NV, RV, (long)NT * WVV, RV);

        fattn_k<<<dim3(8, 1, NZ), 256, FSMEM>>>(qH, qL, kH, kL, vH, vL, tmp);

        cudaMemsetAsync(stats, 0, sizeof(float) * 2 * NH * NV);
        resid_reduce_k<<<dim3(RR / 64, NH), 256>>>(net, tmp, stats, 0);
        bn_apply_k<<<(int)((NH * RV) / 256), 256>>>(net, netH, netL, stats, g1, b1, t);

        gemmW_k<0, 0, 128><<<dim3(2, 32, NH), 256, SMEM128>>>(
            netH, netL, WdH + (long)t * WVV, WdL + (long)t * WVV,
            tmp, (bf16*)0, (bf16*)0, RR, NV, NV, RV, (long)NT * WVV, RV);

        cudaMemsetAsync(stats, 0, sizeof(float) * 2 * NH * NV);
        resid_reduce_k<<<dim3(RR / 64, NH), 256>>>(net, tmp, stats, 1);
        bn_apply_k<<<(int)((NH * RV) / 256), 256>>>(net, netH, netL, stats, g2, b2, t);
    }

    final_k<<<(int)(((long)NB * SQ * NH * NV) / 256), 256>>>(out, net);
}